// round 7
// baseline (speedup 1.0000x reference)
#include <cuda_runtime.h>
#include <cstdint>

#define NROWS 16384
#define DIM   512
#define NCODE 8192

#define LOSS_OFF   8388608
#define IDX_OFF    8388609
#define MD_OFF     8404993
#define COMMIT_OFF 8421377

// CTA tile 128(M) x 256(N), 8 warps (2M x 4N), warp tile 64x64
// int8: k-chunk = 128 elements (128 bytes/row)
#define TM   128
#define TN   256
#define NKC  4                      // 512/128 chunks per n-tile
#define NNT  (NCODE / TN)           // 32
#define TOTAL_CHUNKS (NNT * NKC)    // 128

// dynamic smem: A resident 64K | B 4 stages x 32K | e2f 2K | mbarriers
#define OFF_A    0
#define OFF_B    65536
#define BSTAGE   32768
#define OFF_E2F  196608
#define OFF_MB   198656
#define SMEM_DYN 198720

#define A_BYTES  65536
#define B_CHUNK  32768

// chunk-major, pre-swizzled int8 operands
__device__ signed char g_xq[NROWS * DIM];   // [b][kc 0..3][rr 0..127][128B]
__device__ signed char g_cq[NCODE * DIM];   // [nt*4+kc][rr 0..255][128B]
__device__ float  g_rsx[NROWS];             // 1/sx per x row
__device__ float2 g_e2f[NCODE];             // (e2, 2*se) per code
__device__ int    g_cand[NROWS * 12];

// ---------------------------------------------------------------------------
__device__ __forceinline__ uint32_t smem_u32(const void* p) {
    uint32_t a;
    asm("{ .reg .u64 t; cvta.to.shared.u64 t, %1; cvt.u32.u64 %0, t; }"
        : "=r"(a) : "l"(p));
    return a;
}
__device__ __forceinline__ void ldsm4(uint32_t* r, uint32_t addr) {
    asm volatile("ldmatrix.sync.aligned.m8n8.x4.shared.b16 {%0,%1,%2,%3}, [%4];"
                 : "=r"(r[0]), "=r"(r[1]), "=r"(r[2]), "=r"(r[3]) : "r"(addr));
}
__device__ __forceinline__ void imma(int* c, const uint32_t* a,
                                     uint32_t b0, uint32_t b1) {
    asm volatile(
        "mma.sync.aligned.m16n8k32.row.col.s32.s8.s8.s32 "
        "{%0,%1,%2,%3}, {%4,%5,%6,%7}, {%8,%9}, {%0,%1,%2,%3};"
        : "+r"(c[0]), "+r"(c[1]), "+r"(c[2]), "+r"(c[3])
        : "r"(a[0]), "r"(a[1]), "r"(a[2]), "r"(a[3]), "r"(b0), "r"(b1));
}
__device__ __forceinline__ void bulk_g2s(uint32_t dst, const void* src,
                                         uint32_t bytes, uint32_t mbar) {
    asm volatile(
        "cp.async.bulk.shared::cluster.global.mbarrier::complete_tx::bytes "
        "[%0], [%1], %2, [%3];"
        :: "r"(dst), "l"(src), "r"(bytes), "r"(mbar) : "memory");
}
#define MBAR_INIT(mb, c) asm volatile("mbarrier.init.shared.b64 [%0], %1;" :: "r"(mb), "r"(c) : "memory")
#define MBAR_EXPECT(mb, tx) asm volatile("mbarrier.arrive.expect_tx.shared.b64 _, [%0], %1;" :: "r"(mb), "r"(tx) : "memory")
#define MBAR_WAIT(mb, ph) do {                                              \
    uint32_t _m = (mb), _p = (ph), _d;                                      \
    asm volatile("{ .reg .pred p; mbarrier.try_wait.parity.acquire.cta.shared::cta.b64 p, [%1], %2; selp.b32 %0,1,0,p; }" \
                 : "=r"(_d) : "r"(_m), "r"(_p) : "memory");                 \
    if (!_d) {                                                              \
        asm volatile("{ .reg .pred P1;\nW%=:\n"                             \
            "mbarrier.try_wait.parity.acquire.cta.shared::cta.b64 P1, [%0], %1, 0x989680;\n" \
            "@P1 bra.uni D%=;\nbra.uni W%=;\nD%=:\n}"                       \
            :: "r"(_m), "r"(_p) : "memory");                                \
    }                                                                       \
} while (0)

// ---------------------------------------------------------------------------
// Kernel 0a: per-row int8 quantization of x (warp per row), chunk-major pack
// ---------------------------------------------------------------------------
__global__ void quant_x_kernel(const float* __restrict__ x) {
    int warp = (blockIdx.x * blockDim.x + threadIdx.x) >> 5;
    int lane = threadIdx.x & 31;
    if (warp >= NROWS) return;
    const float4* xr = (const float4*)(x + (size_t)warp * DIM);

    float4 v[4];
#pragma unroll
    for (int i = 0; i < 4; i++) v[i] = xr[lane * 4 + i];

    float m = 0.f;
#pragma unroll
    for (int i = 0; i < 4; i++) {
        m = fmaxf(m, fmaxf(fmaxf(fabsf(v[i].x), fabsf(v[i].y)),
                           fmaxf(fabsf(v[i].z), fabsf(v[i].w))));
    }
#pragma unroll
    for (int o = 16; o > 0; o >>= 1) m = fmaxf(m, __shfl_xor_sync(0xffffffffu, m, o));
    m = fmaxf(m, 1e-30f);
    float q = 127.f / m;        // quantizer scale
    if (lane == 0) g_rsx[warp] = q;   // 1/sx

    uint32_t pk[4];
#pragma unroll
    for (int i = 0; i < 4; i++) {
        int a = __float2int_rn(v[i].x * q) & 0xFF;
        int b = __float2int_rn(v[i].y * q) & 0xFF;
        int c = __float2int_rn(v[i].z * q) & 0xFF;
        int d = __float2int_rn(v[i].w * q) & 0xFF;
        pk[i] = (uint32_t)(a | (b << 8) | (c << 16) | (d << 24));
    }
    int b  = warp >> 7, rr = warp & 127;
    int kc = lane >> 3, gi = lane & 7;
    size_t off = ((size_t)(b * 4 + kc) * 128 + rr) * 128 + ((gi ^ (rr & 7)) << 4);
    *(uint4*)(g_xq + off) = *(uint4*)pk;
}

// ---------------------------------------------------------------------------
// Kernel 0b: codebook quantization + exact norms (warp per code row)
// ---------------------------------------------------------------------------
__global__ void quant_cb_kernel(const float* __restrict__ cb) {
    int warp = (blockIdx.x * blockDim.x + threadIdx.x) >> 5;
    int lane = threadIdx.x & 31;
    if (warp >= NCODE) return;
    const float4* er = (const float4*)(cb + (size_t)warp * DIM);

    float4 v[4];
    float m = 0.f, s = 0.f;
#pragma unroll
    for (int i = 0; i < 4; i++) {
        v[i] = er[lane * 4 + i];
        m = fmaxf(m, fmaxf(fmaxf(fabsf(v[i].x), fabsf(v[i].y)),
                           fmaxf(fabsf(v[i].z), fabsf(v[i].w))));
        s += v[i].x * v[i].x + v[i].y * v[i].y + v[i].z * v[i].z + v[i].w * v[i].w;
    }
#pragma unroll
    for (int o = 16; o > 0; o >>= 1) {
        m = fmaxf(m, __shfl_xor_sync(0xffffffffu, m, o));
        s += __shfl_xor_sync(0xffffffffu, s, o);
    }
    m = fmaxf(m, 1e-30f);
    float q = 127.f / m;
    if (lane == 0) g_e2f[warp] = make_float2(s, 2.f * m / 127.f);  // (e2, 2*se)

    uint32_t pk[4];
#pragma unroll
    for (int i = 0; i < 4; i++) {
        int a = __float2int_rn(v[i].x * q) & 0xFF;
        int b = __float2int_rn(v[i].y * q) & 0xFF;
        int c = __float2int_rn(v[i].z * q) & 0xFF;
        int d = __float2int_rn(v[i].w * q) & 0xFF;
        pk[i] = (uint32_t)(a | (b << 8) | (c << 16) | (d << 24));
    }
    int nt = warp >> 8, rr = warp & 255;
    int kc = lane >> 3, gi = lane & 7;
    size_t off = ((size_t)(nt * 4 + kc) * 256 + rr) * 128 + ((gi ^ (rr & 7)) << 4);
    *(uint4*)(g_cq + off) = *(uint4*)pk;
}

// ---------------------------------------------------------------------------
// Kernel 2: int8 IMMA GEMM + top-3-per-quarter (index embedded in mantissa)
// ---------------------------------------------------------------------------
__global__ __launch_bounds__(256, 1)
void vq_mma_kernel() {
    extern __shared__ __align__(1024) char smem[];
    const uint32_t sb = smem_u32(smem);
    float2* e2fs = (float2*)(smem + OFF_E2F);
    const uint32_t mbA = sb + OFF_MB;
    const uint32_t mbB = sb + OFF_MB + 8;

    const int tid    = threadIdx.x;
    const int lane   = tid & 31;
    const int wid    = tid >> 5;
    const int warp_m = wid >> 2;   // 0..1
    const int warp_n = wid & 3;    // 0..3
    const int blk    = blockIdx.x;
    const int row0   = blk * TM;

    const int rA  = (lane & 7) + ((lane >> 3) & 1) * 8;
    const int cA  = lane >> 4;
    const int rB  = (lane & 7) + (lane >> 4) * 8;
    const int cB  = (lane >> 3) & 1;
    const int swl = lane & 7;
    const uint32_t aRow = (uint32_t)(warp_m * 64 + rA) * 128;
    const uint32_t bRow = (uint32_t)(warp_n * 64 + rB) * 128;
    const int g  = lane >> 2;
    const int t4 = lane & 3;

    if (tid == 0) {
        MBAR_INIT(mbA, 1);
#pragma unroll
        for (int s = 0; s < 4; s++) MBAR_INIT(mbB + s * 8, 1);
    }
    __syncthreads();

    if (tid == 0) {
        MBAR_EXPECT(mbA, A_BYTES);
        const char* asrc = (const char*)g_xq + (size_t)blk * A_BYTES;
#pragma unroll
        for (int kc = 0; kc < 4; kc++)
            bulk_g2s(sb + OFF_A + kc * 16384, asrc + kc * 16384, 16384, mbA);
#pragma unroll
        for (int s = 0; s < 3; s++) {
            MBAR_EXPECT(mbB + s * 8, B_CHUNK);
            bulk_g2s(sb + OFF_B + s * BSTAGE,
                     (const char*)g_cq + (size_t)s * B_CHUNK, B_CHUNK, mbB + s * 8);
        }
    }

    // per-row 1/sx for the 8 row-slots this thread owns
    float rsx8[8];
#pragma unroll
    for (int s = 0; s < 8; s++)
        rsx8[s] = g_rsx[row0 + warp_m * 64 + (s >> 1) * 16 + (s & 1) * 8 + g];

    int acc[4][8][4];
#pragma unroll
    for (int a = 0; a < 4; a++)
#pragma unroll
        for (int b = 0; b < 8; b++)
#pragma unroll
            for (int c = 0; c < 4; c++) acc[a][b][c] = 0;

    // top-3 keys per slot (float with code index in low 13 mantissa bits)
    float m0[8], m1[8], m2[8];
#pragma unroll
    for (int s = 0; s < 8; s++) { m0[s] = 3.4e38f; m1[s] = 3.4e38f; m2[s] = 3.4e38f; }

    MBAR_WAIT(mbA, 0);

#pragma unroll 1
    for (int cc = 0; cc < TOTAL_CHUNKS; cc++) {
        const int kc = cc & 3;          // stage index == kc
        const int nt = cc >> 2;

        MBAR_WAIT(mbB + kc * 8, (cc >> 2) & 1);
        if (kc == 0) e2fs[tid] = g_e2f[nt * TN + tid];

        const uint32_t stB = sb + OFF_B + (uint32_t)kc * BSTAGE;
        const uint32_t stA = sb + OFF_A + (uint32_t)kc * 16384;
#pragma unroll
        for (int ks = 0; ks < 4; ks++) {
            uint32_t ah[4][4], bh[4][4];
            const uint32_t swA = (uint32_t)(((ks * 2 + cA) ^ swl) << 4);
            const uint32_t swB = (uint32_t)(((ks * 2 + cB) ^ swl) << 4);
#pragma unroll
            for (int mi = 0; mi < 4; mi++)
                ldsm4(ah[mi], stA + aRow + mi * 2048 + swA);
#pragma unroll
            for (int np = 0; np < 4; np++)
                ldsm4(bh[np], stB + bRow + np * 2048 + swB);
#pragma unroll
            for (int mi = 0; mi < 4; mi++)
#pragma unroll
                for (int nj = 0; nj < 8; nj++)
                    imma(acc[mi][nj], ah[mi],
                         bh[nj >> 1][(nj & 1) * 2], bh[nj >> 1][(nj & 1) * 2 + 1]);
        }

        if (kc == 3) {
            // epilogue: d' = e2*rsx - (2*se)*acc ; keep top-3 keys per slot
#pragma unroll
            for (int nj = 0; nj < 8; nj++) {
#pragma unroll
                for (int c = 0; c < 2; c++) {
                    const int col = warp_n * 64 + nj * 8 + 2 * t4 + c;
                    const float2 ef = e2fs[col];
                    const uint32_t gcol = (uint32_t)(nt * TN + col);
#pragma unroll
                    for (int s = 0; s < 8; s++) {
                        const int mi = s >> 1, p = s & 1;
                        float facc = (float)acc[mi][nj][p * 2 + c];
                        float d = fmaf(ef.x, rsx8[s], -ef.y * facc);
                        float k = __int_as_float(
                            (__float_as_int(d) & 0xFFFFE000) | gcol);
                        float h0 = fmaxf(m0[s], k);
                        m0[s] = fminf(m0[s], k);
                        float h1 = fmaxf(m1[s], h0);
                        m1[s] = fminf(m1[s], h0);
                        m2[s] = fminf(m2[s], h1);
                        acc[mi][nj][p * 2 + c] = 0;
                    }
                }
            }
        }

        __syncthreads();
        if (tid == 0 && cc + 3 < TOTAL_CHUNKS) {
            const int ns = (cc + 3) & 3;
            MBAR_EXPECT(mbB + ns * 8, B_CHUNK);
            bulk_g2s(sb + OFF_B + (uint32_t)ns * BSTAGE,
                     (const char*)g_cq + (size_t)(cc + 3) * B_CHUNK,
                     B_CHUNK, mbB + ns * 8);
        }
    }

    // cross-lane (t4) merge of top-3 keys, then write 3 candidates/quarter
#pragma unroll
    for (int s = 0; s < 8; s++) {
#pragma unroll
        for (int off = 1; off <= 2; off <<= 1) {
            float k0 = __shfl_xor_sync(0xffffffffu, m0[s], off);
            float k1 = __shfl_xor_sync(0xffffffffu, m1[s], off);
            float k2 = __shfl_xor_sync(0xffffffffu, m2[s], off);
#pragma unroll
            for (int q = 0; q < 3; q++) {
                float k = (q == 0) ? k0 : ((q == 1) ? k1 : k2);
                float h0 = fmaxf(m0[s], k);
                m0[s] = fminf(m0[s], k);
                float h1 = fmaxf(m1[s], h0);
                m1[s] = fminf(m1[s], h0);
                m2[s] = fminf(m2[s], h1);
            }
        }
    }
    if (t4 == 0) {
#pragma unroll
        for (int s = 0; s < 8; s++) {
            int row = row0 + warp_m * 64 + (s >> 1) * 16 + (s & 1) * 8 + g;
            g_cand[row * 12 + warp_n * 3 + 0] = __float_as_int(m0[s]) & 0x1FFF;
            g_cand[row * 12 + warp_n * 3 + 1] = __float_as_int(m1[s]) & 0x1FFF;
            g_cand[row * 12 + warp_n * 3 + 2] = __float_as_int(m2[s]) & 0x1FFF;
        }
    }
}

// ---------------------------------------------------------------------------
// Kernel 3: exact fp32 refine of 12 candidates + gather + outputs
// ---------------------------------------------------------------------------
__global__ __launch_bounds__(384)
void vq_refine_kernel(const float* __restrict__ x,
                      const float* __restrict__ cb,
                      float* __restrict__ out) {
    __shared__ float sv[12];
    __shared__ int   si[12];
    __shared__ int   swin;

    const int row  = blockIdx.x;
    const int tid  = threadIdx.x;
    const int wid  = tid >> 5;
    const int lane = tid & 31;

    int cand = g_cand[row * 12 + wid];
    const float4* x4 = (const float4*)(x  + (size_t)row  * DIM);
    const float4* e4 = (const float4*)(cb + (size_t)cand * DIM);
    float s = 0.f;
#pragma unroll
    for (int i = 0; i < 4; i++) {
        float4 xv = x4[lane + i * 32];
        float4 ev = e4[lane + i * 32];
        float dx = xv.x - ev.x, dy = xv.y - ev.y;
        float dz = xv.z - ev.z, dw = xv.w - ev.w;
        s += dx * dx + dy * dy + dz * dz + dw * dw;
    }
#pragma unroll
    for (int o = 16; o > 0; o >>= 1) s += __shfl_down_sync(0xffffffffu, s, o);
    if (lane == 0) { sv[wid] = s; si[wid] = cand; }
    __syncthreads();

    if (tid == 0) {
        float bv = sv[0]; int bi = si[0];
#pragma unroll
        for (int k = 1; k < 12; k++) {
            float v = sv[k]; int ix = si[k];
            if (v < bv || (v == bv && ix < bi)) { bv = v; bi = ix; }
        }
        out[IDX_OFF + row] = (float)bi;
        out[MD_OFF + row]  = bv;
        swin = bi;
    }
    __syncthreads();

    if (tid < 128) {
        int win = swin;
        const float4* src = (const float4*)(cb + (size_t)win * DIM);
        float4*       dst = (float4*)(out + (size_t)row * DIM);
        dst[tid] = src[tid];
    }
}

// ---------------------------------------------------------------------------
// Kernel 4: deterministic loss reduction
// ---------------------------------------------------------------------------
__global__ void vq_loss_kernel(float* __restrict__ out) {
    __shared__ float s[512];
    int t = threadIdx.x;
    float acc = 0.f;
    for (int i = t; i < NROWS; i += 512) acc += out[MD_OFF + i];
    s[t] = acc;
    __syncthreads();
#pragma unroll
    for (int o = 256; o > 0; o >>= 1) {
        if (t < o) s[t] += s[t + o];
        __syncthreads();
    }
    if (t == 0) {
        out[COMMIT_OFF] = s[0];
        out[LOSS_OFF]   = 1.25f * s[0];
    }
}

// ---------------------------------------------------------------------------
extern "C" void kernel_launch(void* const* d_in, const int* in_sizes, int n_in,
                              void* d_out, int out_size) {
    const float* x  = (const float*)d_in[0];   // [16384, 512]
    const float* cb = (const float*)d_in[1];   // [8192, 512]
    float* out = (float*)d_out;

    cudaFuncSetAttribute(vq_mma_kernel,
                         cudaFuncAttributeMaxDynamicSharedMemorySize, SMEM_DYN);

    quant_x_kernel<<<NROWS / 8, 256>>>(x);
    quant_cb_kernel<<<NCODE / 8, 256>>>(cb);
    vq_mma_kernel<<<NROWS / TM, 256, SMEM_DYN>>>();
    vq_refine_kernel<<<NROWS, 384>>>(x, cb, out);
    vq_loss_kernel<<<1, 512>>>(out);
}

// round 8
// speedup vs baseline: 2.5153x; 2.5153x over previous
#include <cuda_runtime.h>
#include <cuda_fp16.h>
#include <cstdint>

#define NROWS 16384
#define DIM   512
#define NCODE 8192

#define LOSS_OFF   8388608
#define IDX_OFF    8388609
#define MD_OFF     8404993
#define COMMIT_OFF 8421377

// CTA tile 128(M) x 256(N), 8 warps (2M x 4N), warp tile 64x64, k-chunk 64
#define TM   128
#define TN   256
#define KC   64
#define NKC  (DIM / KC)            // 8
#define NNT  (NCODE / TN)          // 32
#define TOTAL_CHUNKS (NNT * NKC)   // 256

// dynamic smem: A resident 128K | B 2 stages x 32K | e2 1K | mbarriers
#define OFF_A    0
#define OFF_B    131072
#define BSTAGE   32768
#define OFF_E2   196608
#define OFF_MB   197632            // afull +0, full0 +8, full1 +16
#define SMEM_DYN 197696

#define A_BYTES  131072
#define B_CHUNK  32768

__device__ float  g_e2[NCODE];
// chunk-major, pre-swizzled packed operands:
// g_xh: [block(128 rows)][kc][row 0..127][128B swizzled row]
// g_ch: [nt(256 rows)*8 + kc][row 0..255][128B swizzled row]
__device__ __half g_xh[NROWS * DIM];
__device__ __half g_ch[NCODE * DIM];
__device__ int    g_cand[NROWS * 8];

// ---------------------------------------------------------------------------
__device__ __forceinline__ uint32_t smem_u32(const void* p) {
    uint32_t a;
    asm("{ .reg .u64 t; cvta.to.shared.u64 t, %1; cvt.u32.u64 %0, t; }"
        : "=r"(a) : "l"(p));
    return a;
}
__device__ __forceinline__ void ldsm4(uint32_t* r, uint32_t addr) {
    asm volatile("ldmatrix.sync.aligned.m8n8.x4.shared.b16 {%0,%1,%2,%3}, [%4];"
                 : "=r"(r[0]), "=r"(r[1]), "=r"(r[2]), "=r"(r[3]) : "r"(addr));
}
// fp16-accumulate HMMA: C/D are 2 regs of packed half2
__device__ __forceinline__ void hmma16(uint32_t* c, const uint32_t* a,
                                       uint32_t b0, uint32_t b1) {
    asm volatile(
        "mma.sync.aligned.m16n8k16.row.col.f16.f16.f16.f16 "
        "{%0,%1}, {%2,%3,%4,%5}, {%6,%7}, {%0,%1};"
        : "+r"(c[0]), "+r"(c[1])
        : "r"(a[0]), "r"(a[1]), "r"(a[2]), "r"(a[3]), "r"(b0), "r"(b1));
}
__device__ __forceinline__ void bulk_g2s(uint32_t dst, const void* src,
                                         uint32_t bytes, uint32_t mbar) {
    asm volatile(
        "cp.async.bulk.shared::cluster.global.mbarrier::complete_tx::bytes "
        "[%0], [%1], %2, [%3];"
        :: "r"(dst), "l"(src), "r"(bytes), "r"(mbar) : "memory");
}
#define MBAR_INIT(mb, c) asm volatile("mbarrier.init.shared.b64 [%0], %1;" :: "r"(mb), "r"(c) : "memory")
#define MBAR_EXPECT(mb, tx) asm volatile("mbarrier.arrive.expect_tx.shared.b64 _, [%0], %1;" :: "r"(mb), "r"(tx) : "memory")
#define MBAR_WAIT(mb, ph) do {                                              \
    uint32_t _m = (mb), _p = (ph), _d;                                      \
    asm volatile("{ .reg .pred p; mbarrier.try_wait.parity.acquire.cta.shared::cta.b64 p, [%1], %2; selp.b32 %0,1,0,p; }" \
                 : "=r"(_d) : "r"(_m), "r"(_p) : "memory");                 \
    if (!_d) {                                                              \
        asm volatile("{ .reg .pred P1;\nW%=:\n"                             \
            "mbarrier.try_wait.parity.acquire.cta.shared::cta.b64 P1, [%0], %1, 0x989680;\n" \
            "@P1 bra.uni D%=;\nbra.uni W%=;\nD%=:\n}"                       \
            :: "r"(_m), "r"(_p) : "memory");                                \
    }                                                                       \
} while (0)

// ---------------------------------------------------------------------------
// Kernel 0: fp16 convert + chunk-major pre-swizzled pack of x and codebook.
// ---------------------------------------------------------------------------
__global__ void split_kernel(const float* __restrict__ x,
                             const float* __restrict__ cb) {
    const int NXG = NROWS * (DIM / 8);
    const int NCG = NCODE * (DIM / 8);
    int i = blockIdx.x * blockDim.x + threadIdx.x;

    const float4* src;
    char* dstbase;
    int row, g;
    size_t tile_off;
    int rr;
    if (i < NXG) {
        src = (const float4*)x;
        dstbase = (char*)g_xh;
        row = i >> 6; g = i & 63;
        int b = row >> 7; rr = row & 127;
        int kc = g >> 3;
        tile_off = ((size_t)(b * 8 + kc) * 128 + rr) * 128;
    } else if (i < NXG + NCG) {
        int j = i - NXG;
        src = (const float4*)cb;
        dstbase = (char*)g_ch;
        row = j >> 6; g = j & 63;
        int nt = row >> 8; rr = row & 255;
        int kc = g >> 3;
        tile_off = ((size_t)(nt * 8 + kc) * 256 + rr) * 128;
    } else return;

    int gi = g & 7;
    float4 v0 = src[(size_t)row * 128 + g * 2];
    float4 v1 = src[(size_t)row * 128 + g * 2 + 1];
    __half2 h[4];
    h[0] = __halves2half2(__float2half_rn(v0.x), __float2half_rn(v0.y));
    h[1] = __halves2half2(__float2half_rn(v0.z), __float2half_rn(v0.w));
    h[2] = __halves2half2(__float2half_rn(v1.x), __float2half_rn(v1.y));
    h[3] = __halves2half2(__float2half_rn(v1.z), __float2half_rn(v1.w));
    uint32_t sw = (uint32_t)((gi ^ (rr & 7)) << 4);
    *(uint4*)(dstbase + tile_off + sw) = *(uint4*)h;
}

// ---------------------------------------------------------------------------
// Kernel 1: codebook squared norms (one warp per row, fp32)
// ---------------------------------------------------------------------------
__global__ void sq_norms_kernel(const float* __restrict__ cb) {
    int warp = (blockIdx.x * blockDim.x + threadIdx.x) >> 5;
    int lane = threadIdx.x & 31;
    if (warp >= NCODE) return;
    const float4* base = (const float4*)(cb + (size_t)warp * DIM);
    float s = 0.f;
#pragma unroll
    for (int i = 0; i < 4; i++) {
        float4 v = base[lane + i * 32];
        s += v.x * v.x + v.y * v.y + v.z * v.z + v.w * v.w;
    }
#pragma unroll
    for (int o = 16; o > 0; o >>= 1) s += __shfl_down_sync(0xffffffffu, s, o);
    if (lane == 0) g_e2[warp] = s;
}

// ---------------------------------------------------------------------------
// Kernel 2: A-resident fp16 GEMM (fp16 accumulate) + top-2-per-quarter
// ---------------------------------------------------------------------------
__global__ __launch_bounds__(256, 1)
void vq_mma_kernel() {
    extern __shared__ __align__(1024) char smem[];
    const uint32_t sb = smem_u32(smem);
    float* e2s = (float*)(smem + OFF_E2);
    const uint32_t mbA  = sb + OFF_MB;
    const uint32_t mbB0 = sb + OFF_MB + 8;

    const int tid    = threadIdx.x;
    const int lane   = tid & 31;
    const int wid    = tid >> 5;
    const int warp_m = wid >> 2;   // 0..1
    const int warp_n = wid & 3;    // 0..3
    const int blk    = blockIdx.x;
    const int row0   = blk * TM;

    const int rA  = (lane & 7) + ((lane >> 3) & 1) * 8;
    const int cA  = lane >> 4;
    const int rB  = (lane & 7) + (lane >> 4) * 8;
    const int cB  = (lane >> 3) & 1;
    const int swl = lane & 7;
    const uint32_t aRow = (uint32_t)(warp_m * 64 + rA) * 128;
    const uint32_t bRow = (uint32_t)(warp_n * 64 + rB) * 128;
    const int g  = lane >> 2;
    const int t4 = lane & 3;

    if (tid == 0) {
        MBAR_INIT(mbA, 1);
        MBAR_INIT(mbB0, 1);
        MBAR_INIT(mbB0 + 8, 1);
    }
    __syncthreads();

    if (tid == 0) {
        MBAR_EXPECT(mbA, A_BYTES);
        const char* asrc = (const char*)g_xh + (size_t)blk * A_BYTES;
#pragma unroll
        for (int kc = 0; kc < 8; kc++)
            bulk_g2s(sb + OFF_A + kc * 16384, asrc + kc * 16384, 16384, mbA);
        MBAR_EXPECT(mbB0, B_CHUNK);
        bulk_g2s(sb + OFF_B, (const char*)g_ch, B_CHUNK, mbB0);
        MBAR_EXPECT(mbB0 + 8, B_CHUNK);
        bulk_g2s(sb + OFF_B + BSTAGE, (const char*)g_ch + B_CHUNK, B_CHUNK, mbB0 + 8);
    }

    // fp16x2 accumulators: [mi][nj][pair], pair p holds rows g (p=0), g+8 (p=1)
    uint32_t acc[4][8][2];
#pragma unroll
    for (int a = 0; a < 4; a++)
#pragma unroll
        for (int b = 0; b < 8; b++) { acc[a][b][0] = 0u; acc[a][b][1] = 0u; }

    float rv0[8], rv1[8];
    int   ri0[8], ri1[8];
#pragma unroll
    for (int s = 0; s < 8; s++) { rv0[s] = 3.4e38f; rv1[s] = 3.4e38f; ri0[s] = 0; ri1[s] = 0; }

    MBAR_WAIT(mbA, 0);

#pragma unroll 1
    for (int cc = 0; cc < TOTAL_CHUNKS; cc++) {
        const int kc = cc & 7;
        const int stg = cc & 1;
        if (kc == 0) e2s[tid] = g_e2[(cc >> 3) * TN + tid];

        MBAR_WAIT(mbB0 + stg * 8, (cc >> 1) & 1);

        const uint32_t stB = sb + OFF_B + (uint32_t)stg * BSTAGE;
        const uint32_t stA = sb + OFF_A + (uint32_t)kc * 16384;
#pragma unroll
        for (int ks = 0; ks < 4; ks++) {
            uint32_t ah[4][4], bh[4][4];
            const uint32_t swA = (uint32_t)(((ks * 2 + cA) ^ swl) << 4);
            const uint32_t swB = (uint32_t)(((ks * 2 + cB) ^ swl) << 4);
#pragma unroll
            for (int mi = 0; mi < 4; mi++)
                ldsm4(ah[mi], stA + aRow + mi * 2048 + swA);
#pragma unroll
            for (int np = 0; np < 4; np++)
                ldsm4(bh[np], stB + bRow + np * 2048 + swB);
#pragma unroll
            for (int mi = 0; mi < 4; mi++)
#pragma unroll
                for (int nj = 0; nj < 8; nj++)
                    hmma16(acc[mi][nj], ah[mi],
                           bh[nj >> 1][(nj & 1) * 2], bh[nj >> 1][(nj & 1) * 2 + 1]);
        }

        if (kc == 7) {
            // ---- epilogue: top-2 per warp_n quarter for this n-tile ----
            const int nt = cc >> 3;
#pragma unroll
            for (int mi = 0; mi < 4; mi++) {
#pragma unroll
                for (int p = 0; p < 2; p++) {
                    const int slot = mi * 2 + p;
                    float v0 = 3.4e38f, v1 = 3.4e38f;
                    int   i0 = 0, i1 = 0;
#pragma unroll
                    for (int nj = 0; nj < 8; nj++) {
                        float2 f = __half22float2(
                            *(__half2*)&acc[mi][nj][p]);
                        acc[mi][nj][p] = 0u;
#pragma unroll
                        for (int c = 0; c < 2; c++) {
                            int col = warp_n * 64 + nj * 8 + 2 * t4 + c;
                            float d = fmaf(-2.f, (c == 0) ? f.x : f.y, e2s[col]);
                            int gi = nt * TN + col;
                            bool lt1 = d < v1;
                            bool lt0 = d < v0;
                            v1 = lt0 ? v0 : (lt1 ? d : v1);
                            i1 = lt0 ? i0 : (lt1 ? gi : i1);
                            v0 = lt0 ? d : v0;
                            i0 = lt0 ? gi : i0;
                        }
                    }
#pragma unroll
                    for (int off = 1; off <= 2; off <<= 1) {
                        float w0 = __shfl_xor_sync(0xffffffffu, v0, off);
                        int   j0 = __shfl_xor_sync(0xffffffffu, i0, off);
                        float w1 = __shfl_xor_sync(0xffffffffu, v1, off);
                        int   j1 = __shfl_xor_sync(0xffffffffu, i1, off);
                        bool a = w0 < v0;
                        float h0 = a ? w0 : v0;  int hi0 = a ? j0 : i0;
                        float l0 = a ? v0 : w0;  int li0 = a ? i0 : j0;
                        float s  = a ? w1 : v1;  int si  = a ? j1 : i1;
                        bool b = l0 < s;
                        v0 = h0; i0 = hi0;
                        v1 = b ? l0 : s; i1 = b ? li0 : si;
                    }
                    {
                        bool a = v0 < rv0[slot];
                        float h0 = a ? v0 : rv0[slot]; int hi0 = a ? i0 : ri0[slot];
                        float l0 = a ? rv0[slot] : v0; int li0 = a ? ri0[slot] : i0;
                        float s  = a ? v1 : rv1[slot]; int si  = a ? i1 : ri1[slot];
                        bool b = l0 < s;
                        rv0[slot] = h0; ri0[slot] = hi0;
                        rv1[slot] = b ? l0 : s; ri1[slot] = b ? li0 : si;
                    }
                }
            }
        }

        __syncthreads();   // all warps done reading stage stg
        if (tid == 0 && cc + 2 < TOTAL_CHUNKS) {
            MBAR_EXPECT(mbB0 + stg * 8, B_CHUNK);
            bulk_g2s(sb + OFF_B + (uint32_t)stg * BSTAGE,
                     (const char*)g_ch + (size_t)(cc + 2) * B_CHUNK,
                     B_CHUNK, mbB0 + stg * 8);
        }
    }

    if (t4 == 0) {
#pragma unroll
        for (int mi = 0; mi < 4; mi++)
#pragma unroll
            for (int p = 0; p < 2; p++) {
                const int slot = mi * 2 + p;
                int row = row0 + warp_m * 64 + mi * 16 + p * 8 + g;
                g_cand[row * 8 + warp_n * 2 + 0] = ri0[slot];
                g_cand[row * 8 + warp_n * 2 + 1] = ri1[slot];
            }
    }
}

// ---------------------------------------------------------------------------
// Kernel 3: exact fp32 refine of 8 candidates + gather + outputs
// ---------------------------------------------------------------------------
__global__ __launch_bounds__(256)
void vq_refine_kernel(const float* __restrict__ x,
                      const float* __restrict__ cb,
                      float* __restrict__ out) {
    __shared__ float sv[8];
    __shared__ int   si[8];
    __shared__ int   swin;

    const int row  = blockIdx.x;
    const int tid  = threadIdx.x;
    const int wid  = tid >> 5;
    const int lane = tid & 31;

    int cand = g_cand[row * 8 + wid];
    const float4* x4 = (const float4*)(x  + (size_t)row  * DIM);
    const float4* e4 = (const float4*)(cb + (size_t)cand * DIM);
    float s = 0.f;
#pragma unroll
    for (int i = 0; i < 4; i++) {
        float4 xv = x4[lane + i * 32];
        float4 ev = e4[lane + i * 32];
        float dx = xv.x - ev.x, dy = xv.y - ev.y;
        float dz = xv.z - ev.z, dw = xv.w - ev.w;
        s += dx * dx + dy * dy + dz * dz + dw * dw;
    }
#pragma unroll
    for (int o = 16; o > 0; o >>= 1) s += __shfl_down_sync(0xffffffffu, s, o);
    if (lane == 0) { sv[wid] = s; si[wid] = cand; }
    __syncthreads();

    if (tid == 0) {
        float bv = sv[0]; int bi = si[0];
#pragma unroll
        for (int k = 1; k < 8; k++) {
            float v = sv[k]; int ix = si[k];
            if (v < bv || (v == bv && ix < bi)) { bv = v; bi = ix; }
        }
        out[IDX_OFF + row] = (float)bi;
        out[MD_OFF + row]  = bv;
        swin = bi;
    }
    __syncthreads();

    if (tid < 128) {
        int win = swin;
        const float4* src = (const float4*)(cb + (size_t)win * DIM);
        float4*       dst = (float4*)(out + (size_t)row * DIM);
        dst[tid] = src[tid];
    }
}

// ---------------------------------------------------------------------------
// Kernel 4: deterministic loss reduction
// ---------------------------------------------------------------------------
__global__ void vq_loss_kernel(float* __restrict__ out) {
    __shared__ float s[512];
    int t = threadIdx.x;
    float acc = 0.f;
    for (int i = t; i < NROWS; i += 512) acc += out[MD_OFF + i];
    s[t] = acc;
    __syncthreads();
#pragma unroll
    for (int o = 256; o > 0; o >>= 1) {
        if (t < o) s[t] += s[t + o];
        __syncthreads();
    }
    if (t == 0) {
        out[COMMIT_OFF] = s[0];
        out[LOSS_OFF]   = 1.25f * s[0];
    }
}

// ---------------------------------------------------------------------------
extern "C" void kernel_launch(void* const* d_in, const int* in_sizes, int n_in,
                              void* d_out, int out_size) {
    const float* x  = (const float*)d_in[0];   // [16384, 512]
    const float* cb = (const float*)d_in[1];   // [8192, 512]
    float* out = (float*)d_out;

    cudaFuncSetAttribute(vq_mma_kernel,
                         cudaFuncAttributeMaxDynamicSharedMemorySize, SMEM_DYN);

    split_kernel<<<(NROWS + NCODE) * (DIM / 8) / 256, 256>>>(x, cb);
    sq_norms_kernel<<<NCODE / 8, 256>>>(cb);
    vq_mma_kernel<<<NROWS / TM, 256, SMEM_DYN>>>();
    vq_refine_kernel<<<NROWS, 256>>>(x, cb, out);
    vq_loss_kernel<<<1, 512>>>(out);
}

// round 9
// speedup vs baseline: 2.5538x; 1.0153x over previous
#include <cuda_runtime.h>
#include <cuda_fp16.h>
#include <cstdint>

#define NROWS 16384
#define DIM   512
#define NCODE 8192

#define LOSS_OFF   8388608
#define IDX_OFF    8388609
#define MD_OFF     8404993
#define COMMIT_OFF 8421377

// CTA tile 128(M) x 256(N), 16 warps (2M x 8N), warp tile 64x32, k-chunk 64
#define TM   128
#define TN   256
#define KC   64
#define NKC  (DIM / KC)            // 8
#define NNT  (NCODE / TN)          // 32
#define TOTAL_CHUNKS (NNT * NKC)   // 256

// dynamic smem: A resident 128K | B 2 stages x 32K | e2 1K | mbar | cand xfer 8K
#define OFF_A    0
#define OFF_B    131072
#define BSTAGE   32768
#define OFF_E2   196608
#define OFF_MB   197632
#define OFF_CAND 197696
#define SMEM_DYN (197696 + 8192)

#define A_BYTES  131072
#define B_CHUNK  32768

__device__ float  g_e2[NCODE];
// chunk-major, pre-swizzled packed operands
__device__ __half g_xh[NROWS * DIM];
__device__ __half g_ch[NCODE * DIM];
__device__ int    g_cand[NROWS * 8];
__device__ float  g_partial[64];

// ---------------------------------------------------------------------------
__device__ __forceinline__ uint32_t smem_u32(const void* p) {
    uint32_t a;
    asm("{ .reg .u64 t; cvta.to.shared.u64 t, %1; cvt.u32.u64 %0, t; }"
        : "=r"(a) : "l"(p));
    return a;
}
__device__ __forceinline__ void ldsm4(uint32_t* r, uint32_t addr) {
    asm volatile("ldmatrix.sync.aligned.m8n8.x4.shared.b16 {%0,%1,%2,%3}, [%4];"
                 : "=r"(r[0]), "=r"(r[1]), "=r"(r[2]), "=r"(r[3]) : "r"(addr));
}
__device__ __forceinline__ void hmma16(uint32_t* c, const uint32_t* a,
                                       uint32_t b0, uint32_t b1) {
    asm volatile(
        "mma.sync.aligned.m16n8k16.row.col.f16.f16.f16.f16 "
        "{%0,%1}, {%2,%3,%4,%5}, {%6,%7}, {%0,%1};"
        : "+r"(c[0]), "+r"(c[1])
        : "r"(a[0]), "r"(a[1]), "r"(a[2]), "r"(a[3]), "r"(b0), "r"(b1));
}
__device__ __forceinline__ void bulk_g2s(uint32_t dst, const void* src,
                                         uint32_t bytes, uint32_t mbar) {
    asm volatile(
        "cp.async.bulk.shared::cluster.global.mbarrier::complete_tx::bytes "
        "[%0], [%1], %2, [%3];"
        :: "r"(dst), "l"(src), "r"(bytes), "r"(mbar) : "memory");
}
#define MBAR_INIT(mb, c) asm volatile("mbarrier.init.shared.b64 [%0], %1;" :: "r"(mb), "r"(c) : "memory")
#define MBAR_EXPECT(mb, tx) asm volatile("mbarrier.arrive.expect_tx.shared.b64 _, [%0], %1;" :: "r"(mb), "r"(tx) : "memory")
#define MBAR_WAIT(mb, ph) do {                                              \
    uint32_t _m = (mb), _p = (ph), _d;                                      \
    asm volatile("{ .reg .pred p; mbarrier.try_wait.parity.acquire.cta.shared::cta.b64 p, [%1], %2; selp.b32 %0,1,0,p; }" \
                 : "=r"(_d) : "r"(_m), "r"(_p) : "memory");                 \
    if (!_d) {                                                              \
        asm volatile("{ .reg .pred P1;\nW%=:\n"                             \
            "mbarrier.try_wait.parity.acquire.cta.shared::cta.b64 P1, [%0], %1, 0x989680;\n" \
            "@P1 bra.uni D%=;\nbra.uni W%=;\nD%=:\n}"                       \
            :: "r"(_m), "r"(_p) : "memory");                                \
    }                                                                       \
} while (0)

// ---------------------------------------------------------------------------
// Kernel 0a: fp16 convert + chunk-major pre-swizzled pack of x
// ---------------------------------------------------------------------------
__global__ void split_x_kernel(const float* __restrict__ x) {
    int i = blockIdx.x * blockDim.x + threadIdx.x;   // group id
    int row = i >> 6, g = i & 63;
    int b = row >> 7, rr = row & 127;
    int kc = g >> 3, gi = g & 7;
    size_t tile_off = ((size_t)(b * 8 + kc) * 128 + rr) * 128;

    const float4* src = (const float4*)x;
    float4 v0 = src[(size_t)row * 128 + g * 2];
    float4 v1 = src[(size_t)row * 128 + g * 2 + 1];
    __half2 h[4];
    h[0] = __halves2half2(__float2half_rn(v0.x), __float2half_rn(v0.y));
    h[1] = __halves2half2(__float2half_rn(v0.z), __float2half_rn(v0.w));
    h[2] = __halves2half2(__float2half_rn(v1.x), __float2half_rn(v1.y));
    h[3] = __halves2half2(__float2half_rn(v1.z), __float2half_rn(v1.w));
    uint32_t sw = (uint32_t)((gi ^ (rr & 7)) << 4);
    *(uint4*)((char*)g_xh + tile_off + sw) = *(uint4*)h;
}

// ---------------------------------------------------------------------------
// Kernel 0b: codebook fp16 pack (chunk-major swizzled) + fused exact norms
// One warp per code row; lane handles groups lane and lane+32.
// ---------------------------------------------------------------------------
__global__ void split_cb_kernel(const float* __restrict__ cb) {
    int row  = (blockIdx.x * blockDim.x + threadIdx.x) >> 5;
    int lane = threadIdx.x & 31;
    if (row >= NCODE) return;
    const float4* r4 = (const float4*)(cb + (size_t)row * DIM);
    int nt = row >> 8, rr = row & 255;

    float s = 0.f;
#pragma unroll
    for (int q = 0; q < 2; q++) {
        int gg = lane + q * 32;
        float4 v0 = r4[gg * 2];
        float4 v1 = r4[gg * 2 + 1];
        s += v0.x * v0.x + v0.y * v0.y + v0.z * v0.z + v0.w * v0.w;
        s += v1.x * v1.x + v1.y * v1.y + v1.z * v1.z + v1.w * v1.w;
        __half2 h[4];
        h[0] = __halves2half2(__float2half_rn(v0.x), __float2half_rn(v0.y));
        h[1] = __halves2half2(__float2half_rn(v0.z), __float2half_rn(v0.w));
        h[2] = __halves2half2(__float2half_rn(v1.x), __float2half_rn(v1.y));
        h[3] = __halves2half2(__float2half_rn(v1.z), __float2half_rn(v1.w));
        int kc = gg >> 3, gi = gg & 7;
        size_t off = ((size_t)(nt * 8 + kc) * 256 + rr) * 128
                   + (size_t)((gi ^ (rr & 7)) << 4);
        *(uint4*)((char*)g_ch + off) = *(uint4*)h;
    }
#pragma unroll
    for (int o = 16; o > 0; o >>= 1) s += __shfl_down_sync(0xffffffffu, s, o);
    if (lane == 0) g_e2[row] = s;
}

// ---------------------------------------------------------------------------
// Kernel 2: A-resident fp16 GEMM, 512 threads, top-2 per warp slice,
//           exact pairwise merge to top-2 per 64-col quarter at the end.
// ---------------------------------------------------------------------------
__global__ __launch_bounds__(512, 1)
void vq_mma_kernel() {
    extern __shared__ __align__(1024) char smem[];
    const uint32_t sb = smem_u32(smem);
    float* e2s = (float*)(smem + OFF_E2);
    float4* cxf = (float4*)(smem + OFF_CAND);
    const uint32_t mbA  = sb + OFF_MB;
    const uint32_t mbB0 = sb + OFF_MB + 8;

    const int tid    = threadIdx.x;
    const int lane   = tid & 31;
    const int wid    = tid >> 5;
    const int warp_m = wid >> 3;   // 0..1
    const int warp_n = wid & 7;    // 0..7 (32-col slices)
    const int blk    = blockIdx.x;
    const int row0   = blk * TM;

    const int rA  = (lane & 7) + ((lane >> 3) & 1) * 8;
    const int cA  = lane >> 4;
    const int rB  = (lane & 7) + (lane >> 4) * 8;
    const int cB  = (lane >> 3) & 1;
    const int swl = lane & 7;
    const uint32_t aRow = (uint32_t)(warp_m * 64 + rA) * 128;
    const uint32_t bRow = (uint32_t)(warp_n * 32 + rB) * 128;
    const int g  = lane >> 2;
    const int t4 = lane & 3;

    if (tid == 0) {
        MBAR_INIT(mbA, 1);
        MBAR_INIT(mbB0, 1);
        MBAR_INIT(mbB0 + 8, 1);
    }
    __syncthreads();

    if (tid == 0) {
        MBAR_EXPECT(mbA, A_BYTES);
        const char* asrc = (const char*)g_xh + (size_t)blk * A_BYTES;
#pragma unroll
        for (int kc = 0; kc < 8; kc++)
            bulk_g2s(sb + OFF_A + kc * 16384, asrc + kc * 16384, 16384, mbA);
        MBAR_EXPECT(mbB0, B_CHUNK);
        bulk_g2s(sb + OFF_B, (const char*)g_ch, B_CHUNK, mbB0);
        MBAR_EXPECT(mbB0 + 8, B_CHUNK);
        bulk_g2s(sb + OFF_B + BSTAGE, (const char*)g_ch + B_CHUNK, B_CHUNK, mbB0 + 8);
    }

    // fp16x2 accumulators: [mi][nj][pair]
    uint32_t acc[4][4][2];
#pragma unroll
    for (int a = 0; a < 4; a++)
#pragma unroll
        for (int b = 0; b < 4; b++) { acc[a][b][0] = 0u; acc[a][b][1] = 0u; }

    // running top-2 per row-slot over this warp's 32-col slices
    float rv0[8], rv1[8];
    int   ri0[8], ri1[8];
#pragma unroll
    for (int s = 0; s < 8; s++) { rv0[s] = 3.4e38f; rv1[s] = 3.4e38f; ri0[s] = 0; ri1[s] = 0; }

    MBAR_WAIT(mbA, 0);

#pragma unroll 1
    for (int cc = 0; cc < TOTAL_CHUNKS; cc++) {
        const int kc = cc & 7;
        const int stg = cc & 1;
        if (kc == 0 && tid < 256) e2s[tid] = g_e2[(cc >> 3) * TN + tid];

        MBAR_WAIT(mbB0 + stg * 8, (cc >> 1) & 1);

        const uint32_t stB = sb + OFF_B + (uint32_t)stg * BSTAGE;
        const uint32_t stA = sb + OFF_A + (uint32_t)kc * 16384;
#pragma unroll
        for (int ks = 0; ks < 4; ks++) {
            uint32_t ah[4][4], bh[2][4];
            const uint32_t swA = (uint32_t)(((ks * 2 + cA) ^ swl) << 4);
            const uint32_t swB = (uint32_t)(((ks * 2 + cB) ^ swl) << 4);
#pragma unroll
            for (int mi = 0; mi < 4; mi++)
                ldsm4(ah[mi], stA + aRow + mi * 2048 + swA);
#pragma unroll
            for (int np = 0; np < 2; np++)
                ldsm4(bh[np], stB + bRow + np * 2048 + swB);
#pragma unroll
            for (int mi = 0; mi < 4; mi++)
#pragma unroll
                for (int nj = 0; nj < 4; nj++)
                    hmma16(acc[mi][nj], ah[mi],
                           bh[nj >> 1][(nj & 1) * 2], bh[nj >> 1][(nj & 1) * 2 + 1]);
        }

        if (kc == 7) {
            const int nt = cc >> 3;
#pragma unroll
            for (int mi = 0; mi < 4; mi++) {
#pragma unroll
                for (int p = 0; p < 2; p++) {
                    const int slot = mi * 2 + p;
                    float v0 = 3.4e38f, v1 = 3.4e38f;
                    int   i0 = 0, i1 = 0;
#pragma unroll
                    for (int nj = 0; nj < 4; nj++) {
                        float2 f = __half22float2(*(__half2*)&acc[mi][nj][p]);
                        acc[mi][nj][p] = 0u;
#pragma unroll
                        for (int c = 0; c < 2; c++) {
                            int col = warp_n * 32 + nj * 8 + 2 * t4 + c;
                            float d = fmaf(-2.f, (c == 0) ? f.x : f.y, e2s[col]);
                            int gi = nt * TN + col;
                            bool lt1 = d < v1;
                            bool lt0 = d < v0;
                            v1 = lt0 ? v0 : (lt1 ? d : v1);
                            i1 = lt0 ? i0 : (lt1 ? gi : i1);
                            v0 = lt0 ? d : v0;
                            i0 = lt0 ? gi : i0;
                        }
                    }
#pragma unroll
                    for (int off = 1; off <= 2; off <<= 1) {
                        float w0 = __shfl_xor_sync(0xffffffffu, v0, off);
                        int   j0 = __shfl_xor_sync(0xffffffffu, i0, off);
                        float w1 = __shfl_xor_sync(0xffffffffu, v1, off);
                        int   j1 = __shfl_xor_sync(0xffffffffu, i1, off);
                        bool a = w0 < v0;
                        float h0 = a ? w0 : v0;  int hi0 = a ? j0 : i0;
                        float l0 = a ? v0 : w0;  int li0 = a ? i0 : j0;
                        float s  = a ? w1 : v1;  int si  = a ? j1 : i1;
                        bool b = l0 < s;
                        v0 = h0; i0 = hi0;
                        v1 = b ? l0 : s; i1 = b ? li0 : si;
                    }
                    {
                        bool a = v0 < rv0[slot];
                        float h0 = a ? v0 : rv0[slot]; int hi0 = a ? i0 : ri0[slot];
                        float l0 = a ? rv0[slot] : v0; int li0 = a ? ri0[slot] : i0;
                        float s  = a ? v1 : rv1[slot]; int si  = a ? i1 : ri1[slot];
                        bool b = l0 < s;
                        rv0[slot] = h0; ri0[slot] = hi0;
                        rv1[slot] = b ? l0 : s; ri1[slot] = b ? li0 : si;
                    }
                }
            }
        }

        __syncthreads();
        if (tid == 0 && cc + 2 < TOTAL_CHUNKS) {
            MBAR_EXPECT(mbB0 + stg * 8, B_CHUNK);
            bulk_g2s(sb + OFF_B + (uint32_t)stg * BSTAGE,
                     (const char*)g_ch + (size_t)(cc + 2) * B_CHUNK,
                     B_CHUNK, mbB0 + stg * 8);
        }
    }

    // ---- final: merge odd/even warp slices into top-2 per 64-col quarter ----
    const int pairgrp = warp_m * 4 + (warp_n >> 1);   // 0..7
    if ((warp_n & 1) && t4 == 0) {
#pragma unroll
        for (int s = 0; s < 8; s++) {
            int rowin = (s >> 1) * 16 + (s & 1) * 8 + g;
            cxf[pairgrp * 64 + rowin] =
                make_float4(rv0[s], rv1[s],
                            __int_as_float(ri0[s]), __int_as_float(ri1[s]));
        }
    }
    __syncthreads();
    if (!(warp_n & 1) && t4 == 0) {
#pragma unroll
        for (int s = 0; s < 8; s++) {
            int rowin = (s >> 1) * 16 + (s & 1) * 8 + g;
            float4 o = cxf[pairgrp * 64 + rowin];
            float ov0 = o.x, ov1 = o.y;
            int   oi0 = __float_as_int(o.z), oi1 = __float_as_int(o.w);
            bool a = ov0 < rv0[s];
            float h0 = a ? ov0 : rv0[s]; int hi0 = a ? oi0 : ri0[s];
            float l0 = a ? rv0[s] : ov0; int li0 = a ? ri0[s] : oi0;
            float sc = a ? ov1 : rv1[s]; int sci = a ? oi1 : ri1[s];
            bool b = l0 < sc;
            float m1 = b ? l0 : sc; int m1i = b ? li0 : sci;
            int row = row0 + warp_m * 64 + rowin;
            g_cand[row * 8 + (warp_n >> 1) * 2 + 0] = hi0;
            g_cand[row * 8 + (warp_n >> 1) * 2 + 1] = m1i;
        }
    }
}

// ---------------------------------------------------------------------------
// Kernel 3: exact fp32 refine of 8 candidates + gather + outputs
// ---------------------------------------------------------------------------
__global__ __launch_bounds__(256)
void vq_refine_kernel(const float* __restrict__ x,
                      const float* __restrict__ cb,
                      float* __restrict__ out) {
    __shared__ float sv[8];
    __shared__ int   si[8];
    __shared__ int   swin;

    const int row  = blockIdx.x;
    const int tid  = threadIdx.x;
    const int wid  = tid >> 5;
    const int lane = tid & 31;

    int cand = g_cand[row * 8 + wid];
    const float4* x4 = (const float4*)(x  + (size_t)row  * DIM);
    const float4* e4 = (const float4*)(cb + (size_t)cand * DIM);
    float s = 0.f;
#pragma unroll
    for (int i = 0; i < 4; i++) {
        float4 xv = x4[lane + i * 32];
        float4 ev = e4[lane + i * 32];
        float dx = xv.x - ev.x, dy = xv.y - ev.y;
        float dz = xv.z - ev.z, dw = xv.w - ev.w;
        s += dx * dx + dy * dy + dz * dz + dw * dw;
    }
#pragma unroll
    for (int o = 16; o > 0; o >>= 1) s += __shfl_down_sync(0xffffffffu, s, o);
    if (lane == 0) { sv[wid] = s; si[wid] = cand; }
    __syncthreads();

    if (tid == 0) {
        float bv = sv[0]; int bi = si[0];
#pragma unroll
        for (int k = 1; k < 8; k++) {
            float v = sv[k]; int ix = si[k];
            if (v < bv || (v == bv && ix < bi)) { bv = v; bi = ix; }
        }
        out[IDX_OFF + row] = (float)bi;
        out[MD_OFF + row]  = bv;
        swin = bi;
    }
    __syncthreads();

    if (tid < 128) {
        int win = swin;
        const float4* src = (const float4*)(cb + (size_t)win * DIM);
        float4*       dst = (float4*)(out + (size_t)row * DIM);
        dst[tid] = src[tid];
    }
}

// ---------------------------------------------------------------------------
// Kernel 4a/4b: deterministic two-stage loss reduction
// ---------------------------------------------------------------------------
__global__ void vq_loss1_kernel(const float* __restrict__ out) {
    __shared__ float s[256];
    int t = threadIdx.x;
    int base = blockIdx.x * 256;
    s[t] = out[MD_OFF + base + t];
    __syncthreads();
#pragma unroll
    for (int o = 128; o > 0; o >>= 1) {
        if (t < o) s[t] += s[t + o];
        __syncthreads();
    }
    if (t == 0) g_partial[blockIdx.x] = s[0];
}
__global__ void vq_loss2_kernel(float* __restrict__ out) {
    __shared__ float s[64];
    int t = threadIdx.x;
    s[t] = g_partial[t];
    __syncthreads();
#pragma unroll
    for (int o = 32; o > 0; o >>= 1) {
        if (t < o) s[t] += s[t + o];
        __syncthreads();
    }
    if (t == 0) {
        out[COMMIT_OFF] = s[0];
        out[LOSS_OFF]   = 1.25f * s[0];
    }
}

// ---------------------------------------------------------------------------
extern "C" void kernel_launch(void* const* d_in, const int* in_sizes, int n_in,
                              void* d_out, int out_size) {
    const float* x  = (const float*)d_in[0];   // [16384, 512]
    const float* cb = (const float*)d_in[1];   // [8192, 512]
    float* out = (float*)d_out;

    cudaFuncSetAttribute(vq_mma_kernel,
                         cudaFuncAttributeMaxDynamicSharedMemorySize, SMEM_DYN);

    split_x_kernel<<<NROWS * (DIM / 8) / 256, 256>>>(x);
    split_cb_kernel<<<NCODE / 8, 256>>>(cb);
    vq_mma_kernel<<<NROWS / TM, 512, SMEM_DYN>>>();
    vq_refine_kernel<<<NROWS, 256>>>(x, cb, out);
    vq_loss1_kernel<<<64, 256>>>(out);
    vq_loss2_kernel<<<1, 64>>>(out);
}

// round 10
// speedup vs baseline: 2.6787x; 1.0489x over previous
#include <cuda_runtime.h>
#include <cuda_fp16.h>
#include <cstdint>

#define NROWS 16384
#define DIM   512
#define NCODE 8192

#define LOSS_OFF   8388608
#define IDX_OFF    8388609
#define MD_OFF     8404993
#define COMMIT_OFF 8421377

// 148 CTAs: 136 x 112 rows + 12 x 96 rows = 16384. One CTA per SM (one wave).
#define NCTA  148
#define NBIG  136
#define TMBIG 112
#define TMSML 96
#define BIGROWS_END 15232            // 136*112
#define ABASE_SML   15597568ULL     // 15232*1024 bytes

#define TN   256
#define NKC  8                      // k-chunks of 64 per n-tile
#define NNT  (NCODE / TN)           // 32
#define TOTAL_CHUNKS (NNT * NKC)    // 256

// dynamic smem: A (max 112K+) | B 2 x 32K | e2 1K | cand 14K | mbar
#define OFF_A    0
#define A_MAX    114688             // 112*1024
#define OFF_B    114688
#define BSTAGE   32768
#define OFF_E2   180224
#define OFF_CAND 181248             // 8 warps * 112 rows * 16B = 14336
#define OFF_MB   195584
#define SMEM_DYN 195648

#define B_CHUNK  32768

__device__ float  g_e2[NCODE];
// chunk-major, pre-swizzled packed operands (A packed per-CTA, variable rows)
__device__ __half g_xh[NROWS * DIM];
__device__ __half g_ch[NCODE * DIM];
__device__ int    g_cand[NROWS * 8];
__device__ float  g_partial[64];

// ---------------------------------------------------------------------------
__device__ __forceinline__ uint32_t smem_u32(const void* p) {
    uint32_t a;
    asm("{ .reg .u64 t; cvta.to.shared.u64 t, %1; cvt.u32.u64 %0, t; }"
        : "=r"(a) : "l"(p));
    return a;
}
__device__ __forceinline__ void ldsm4(uint32_t* r, uint32_t addr) {
    asm volatile("ldmatrix.sync.aligned.m8n8.x4.shared.b16 {%0,%1,%2,%3}, [%4];"
                 : "=r"(r[0]), "=r"(r[1]), "=r"(r[2]), "=r"(r[3]) : "r"(addr));
}
__device__ __forceinline__ void hmma16(uint32_t* c, const uint32_t* a,
                                       uint32_t b0, uint32_t b1) {
    asm volatile(
        "mma.sync.aligned.m16n8k16.row.col.f16.f16.f16.f16 "
        "{%0,%1}, {%2,%3,%4,%5}, {%6,%7}, {%0,%1};"
        : "+r"(c[0]), "+r"(c[1])
        : "r"(a[0]), "r"(a[1]), "r"(a[2]), "r"(a[3]), "r"(b0), "r"(b1));
}
__device__ __forceinline__ void bulk_g2s(uint32_t dst, const void* src,
                                         uint32_t bytes, uint32_t mbar) {
    asm volatile(
        "cp.async.bulk.shared::cluster.global.mbarrier::complete_tx::bytes "
        "[%0], [%1], %2, [%3];"
        :: "r"(dst), "l"(src), "r"(bytes), "r"(mbar) : "memory");
}
#define MBAR_INIT(mb, c) asm volatile("mbarrier.init.shared.b64 [%0], %1;" :: "r"(mb), "r"(c) : "memory")
#define MBAR_EXPECT(mb, tx) asm volatile("mbarrier.arrive.expect_tx.shared.b64 _, [%0], %1;" :: "r"(mb), "r"(tx) : "memory")
#define MBAR_WAIT(mb, ph) do {                                              \
    uint32_t _m = (mb), _p = (ph), _d;                                      \
    asm volatile("{ .reg .pred p; mbarrier.try_wait.parity.acquire.cta.shared::cta.b64 p, [%1], %2; selp.b32 %0,1,0,p; }" \
                 : "=r"(_d) : "r"(_m), "r"(_p) : "memory");                 \
    if (!_d) {                                                              \
        asm volatile("{ .reg .pred P1;\nW%=:\n"                             \
            "mbarrier.try_wait.parity.acquire.cta.shared::cta.b64 P1, [%0], %1, 0x989680;\n" \
            "@P1 bra.uni D%=;\nbra.uni W%=;\nD%=:\n}"                       \
            :: "r"(_m), "r"(_p) : "memory");                                \
    }                                                                       \
} while (0)

// ---------------------------------------------------------------------------
// Kernel 0a: fp16 convert + per-CTA chunk-major pre-swizzled pack of x
// ---------------------------------------------------------------------------
__global__ void split_x_kernel(const float* __restrict__ x) {
    int i = blockIdx.x * blockDim.x + threadIdx.x;   // group id (row*64 + g)
    int r = i >> 6, g = i & 63;

    int rr, rows;
    size_t base;
    if (r < BIGROWS_END) {
        int c = r / 112; rr = r - c * 112; rows = 112;
        base = (size_t)c * 114688;
    } else {
        int t = r - BIGROWS_END;
        int ci = t / 96; rr = t - ci * 96; rows = 96;
        base = ABASE_SML + (size_t)ci * 98304;
    }
    int kc = g >> 3, gi = g & 7;
    size_t off = base + (size_t)kc * rows * 128 + (size_t)rr * 128
               + (size_t)((gi ^ (rr & 7)) << 4);

    const float4* src = (const float4*)x;
    float4 v0 = src[(size_t)r * 128 + g * 2];
    float4 v1 = src[(size_t)r * 128 + g * 2 + 1];
    __half2 h[4];
    h[0] = __halves2half2(__float2half_rn(v0.x), __float2half_rn(v0.y));
    h[1] = __halves2half2(__float2half_rn(v0.z), __float2half_rn(v0.w));
    h[2] = __halves2half2(__float2half_rn(v1.x), __float2half_rn(v1.y));
    h[3] = __halves2half2(__float2half_rn(v1.z), __float2half_rn(v1.w));
    *(uint4*)((char*)g_xh + off) = *(uint4*)h;
}

// ---------------------------------------------------------------------------
// Kernel 0b: codebook fp16 pack (chunk-major swizzled) + fused exact norms
// ---------------------------------------------------------------------------
__global__ void split_cb_kernel(const float* __restrict__ cb) {
    int row  = (blockIdx.x * blockDim.x + threadIdx.x) >> 5;
    int lane = threadIdx.x & 31;
    if (row >= NCODE) return;
    const float4* r4 = (const float4*)(cb + (size_t)row * DIM);
    int nt = row >> 8, rr = row & 255;

    float s = 0.f;
#pragma unroll
    for (int q = 0; q < 2; q++) {
        int gg = lane + q * 32;
        float4 v0 = r4[gg * 2];
        float4 v1 = r4[gg * 2 + 1];
        s += v0.x * v0.x + v0.y * v0.y + v0.z * v0.z + v0.w * v0.w;
        s += v1.x * v1.x + v1.y * v1.y + v1.z * v1.z + v1.w * v1.w;
        __half2 h[4];
        h[0] = __halves2half2(__float2half_rn(v0.x), __float2half_rn(v0.y));
        h[1] = __halves2half2(__float2half_rn(v0.z), __float2half_rn(v0.w));
        h[2] = __halves2half2(__float2half_rn(v1.x), __float2half_rn(v1.y));
        h[3] = __halves2half2(__float2half_rn(v1.z), __float2half_rn(v1.w));
        int kc = gg >> 3, gi = gg & 7;
        size_t off = ((size_t)(nt * 8 + kc) * 256 + rr) * 128
                   + (size_t)((gi ^ (rr & 7)) << 4);
        *(uint4*)((char*)g_ch + off) = *(uint4*)h;
    }
#pragma unroll
    for (int o = 16; o > 0; o >>= 1) s += __shfl_down_sync(0xffffffffu, s, o);
    if (lane == 0) g_e2[row] = s;
}

// ---------------------------------------------------------------------------
// Kernel 2: balanced 148-CTA A-resident fp16 GEMM + top-2 per 64-col quarter
// 256 threads = 8 warps, warp w covers all rows x cols [w*32, w*32+32).
// ---------------------------------------------------------------------------
__global__ __launch_bounds__(256, 1)
void vq_mma_kernel() {
    extern __shared__ __align__(1024) char smem[];
    const uint32_t sb = smem_u32(smem);
    float*  e2s = (float*)(smem + OFF_E2);
    float4* cxf = (float4*)(smem + OFF_CAND);
    const uint32_t mbA  = sb + OFF_MB;
    const uint32_t mbB0 = sb + OFF_MB + 8;

    const int tid  = threadIdx.x;
    const int lane = tid & 31;
    const int wid  = tid >> 5;          // warp = 32-col slice
    const int blk  = blockIdx.x;

    const int ROWS   = (blk < NBIG) ? TMBIG : TMSML;
    const int MI     = (blk < NBIG) ? 7 : 6;
    const int rowbase = (blk < NBIG) ? blk * 112
                                     : BIGROWS_END + (blk - NBIG) * 96;
    const size_t abase = (blk < NBIG) ? (size_t)blk * 114688
                                      : ABASE_SML + (size_t)(blk - NBIG) * 98304;
    const uint32_t ACH = (uint32_t)ROWS * 128;   // A chunk bytes per kc

    const int rA  = (lane & 7) + ((lane >> 3) & 1) * 8;
    const int cA  = lane >> 4;
    const int rB  = (lane & 7) + (lane >> 4) * 8;
    const int cB  = (lane >> 3) & 1;
    const int swl = lane & 7;
    const uint32_t bRow = (uint32_t)(wid * 32 + rB) * 128;
    const int g  = lane >> 2;
    const int t4 = lane & 3;

    // init running-candidate smem (top-2 per warp-slice per row)
    for (int idx = tid; idx < 8 * 112; idx += 256)
        cxf[idx] = make_float4(3.4e38f, 3.4e38f, 0.f, 0.f);

    if (tid == 0) {
        MBAR_INIT(mbA, 1);
        MBAR_INIT(mbB0, 1);
        MBAR_INIT(mbB0 + 8, 1);
    }
    __syncthreads();

    if (tid == 0) {
        MBAR_EXPECT(mbA, ACH * 8);
        const char* asrc = (const char*)g_xh + abase;
#pragma unroll
        for (int kc = 0; kc < 8; kc++)
            bulk_g2s(sb + OFF_A + kc * ACH, asrc + (size_t)kc * ACH, ACH, mbA);
        MBAR_EXPECT(mbB0, B_CHUNK);
        bulk_g2s(sb + OFF_B, (const char*)g_ch, B_CHUNK, mbB0);
        MBAR_EXPECT(mbB0 + 8, B_CHUNK);
        bulk_g2s(sb + OFF_B + BSTAGE, (const char*)g_ch + B_CHUNK, B_CHUNK, mbB0 + 8);
    }

    // fp16x2 accumulators: [mi][nj][pair]
    uint32_t acc[7][4][2];
#pragma unroll
    for (int a = 0; a < 7; a++)
#pragma unroll
        for (int b = 0; b < 4; b++) { acc[a][b][0] = 0u; acc[a][b][1] = 0u; }

    MBAR_WAIT(mbA, 0);

#pragma unroll 1
    for (int cc = 0; cc < TOTAL_CHUNKS; cc++) {
        const int kc = cc & 7;
        const int stg = cc & 1;
        if (kc == 0) e2s[tid] = g_e2[(cc >> 3) * TN + tid];

        MBAR_WAIT(mbB0 + stg * 8, (cc >> 1) & 1);

        const uint32_t stB = sb + OFF_B + (uint32_t)stg * BSTAGE;
        const uint32_t stA = sb + OFF_A + (uint32_t)kc * ACH;
#pragma unroll
        for (int ks = 0; ks < 4; ks++) {
            uint32_t ah[7][4], bh[2][4];
            const uint32_t swA = (uint32_t)(((ks * 2 + cA) ^ swl) << 4);
            const uint32_t swB = (uint32_t)(((ks * 2 + cB) ^ swl) << 4);
#pragma unroll
            for (int np = 0; np < 2; np++)
                ldsm4(bh[np], stB + bRow + np * 2048 + swB);
#pragma unroll
            for (int mi = 0; mi < 7; mi++)
                if (mi < MI)
                    ldsm4(ah[mi], stA + (uint32_t)(mi * 16 + rA) * 128 + swA);
#pragma unroll
            for (int mi = 0; mi < 7; mi++)
                if (mi < MI)
#pragma unroll
                    for (int nj = 0; nj < 4; nj++)
                        hmma16(acc[mi][nj], ah[mi],
                               bh[nj >> 1][(nj & 1) * 2],
                               bh[nj >> 1][(nj & 1) * 2 + 1]);
        }

        if (kc == 7) {
            const int nt = cc >> 3;
#pragma unroll
            for (int mi = 0; mi < 7; mi++) {
                if (mi >= MI) continue;
#pragma unroll
                for (int p = 0; p < 2; p++) {
                    float v0 = 3.4e38f, v1 = 3.4e38f;
                    int   i0 = 0, i1 = 0;
#pragma unroll
                    for (int nj = 0; nj < 4; nj++) {
                        float2 f = __half22float2(*(__half2*)&acc[mi][nj][p]);
                        acc[mi][nj][p] = 0u;
#pragma unroll
                        for (int c = 0; c < 2; c++) {
                            int col = wid * 32 + nj * 8 + 2 * t4 + c;
                            float d = fmaf(-2.f, (c == 0) ? f.x : f.y, e2s[col]);
                            int gi = nt * TN + col;
                            bool lt1 = d < v1;
                            bool lt0 = d < v0;
                            v1 = lt0 ? v0 : (lt1 ? d : v1);
                            i1 = lt0 ? i0 : (lt1 ? gi : i1);
                            v0 = lt0 ? d : v0;
                            i0 = lt0 ? gi : i0;
                        }
                    }
#pragma unroll
                    for (int off = 1; off <= 2; off <<= 1) {
                        float w0 = __shfl_xor_sync(0xffffffffu, v0, off);
                        int   j0 = __shfl_xor_sync(0xffffffffu, i0, off);
                        float w1 = __shfl_xor_sync(0xffffffffu, v1, off);
                        int   j1 = __shfl_xor_sync(0xffffffffu, i1, off);
                        bool a = w0 < v0;
                        float h0 = a ? w0 : v0;  int hi0 = a ? j0 : i0;
                        float l0 = a ? v0 : w0;  int li0 = a ? i0 : j0;
                        float s  = a ? w1 : v1;  int si  = a ? j1 : i1;
                        bool b = l0 < s;
                        v0 = h0; i0 = hi0;
                        v1 = b ? l0 : s; i1 = b ? li0 : si;
                    }
                    if (t4 == 0) {
                        int rowin = mi * 16 + p * 8 + g;
                        float4 cur = cxf[wid * 112 + rowin];
                        float cv0 = cur.x, cv1 = cur.y;
                        int ci0 = __float_as_int(cur.z), ci1 = __float_as_int(cur.w);
                        bool a = v0 < cv0;
                        float h0 = a ? v0 : cv0; int hi0 = a ? i0 : ci0;
                        float l0 = a ? cv0 : v0; int li0 = a ? ci0 : i0;
                        float s  = a ? v1 : cv1; int si  = a ? i1 : ci1;
                        bool b = l0 < s;
                        cxf[wid * 112 + rowin] = make_float4(
                            h0, b ? l0 : s,
                            __int_as_float(hi0), __int_as_float(b ? li0 : si));
                    }
                }
            }
        }

        __syncthreads();
        if (tid == 0 && cc + 2 < TOTAL_CHUNKS) {
            MBAR_EXPECT(mbB0 + stg * 8, B_CHUNK);
            bulk_g2s(sb + OFF_B + (uint32_t)stg * BSTAGE,
                     (const char*)g_ch + (size_t)(cc + 2) * B_CHUNK,
                     B_CHUNK, mbB0 + stg * 8);
        }
    }

    // ---- final: merge warp pairs (2q, 2q+1) -> top-2 per 64-col quarter ----
    if (wid < 4) {
        const int q = wid;
#pragma unroll
        for (int j = 0; j < 4; j++) {
            int row = lane + j * 32;
            if (row < ROWS) {
                float4 A = cxf[(2 * q) * 112 + row];
                float4 B = cxf[(2 * q + 1) * 112 + row];
                float av0 = A.x, av1 = A.y, bv0 = B.x, bv1 = B.y;
                int ai0 = __float_as_int(A.z), ai1 = __float_as_int(A.w);
                int bi0 = __float_as_int(B.z), bi1 = __float_as_int(B.w);
                bool a = av0 < bv0;
                float h0 = a ? av0 : bv0; int hi0 = a ? ai0 : bi0;
                float l0 = a ? bv0 : av0; int li0 = a ? bi0 : ai0;
                float s  = a ? av1 : bv1; int si  = a ? ai1 : bi1;
                bool b = l0 < s;
                int m1i = b ? li0 : si;
                int grow = rowbase + row;
                g_cand[grow * 8 + q * 2 + 0] = hi0;
                g_cand[grow * 8 + q * 2 + 1] = m1i;
            }
        }
    }
}

// ---------------------------------------------------------------------------
// Kernel 3: exact fp32 refine of 8 candidates + gather + outputs
// ---------------------------------------------------------------------------
__global__ __launch_bounds__(256)
void vq_refine_kernel(const float* __restrict__ x,
                      const float* __restrict__ cb,
                      float* __restrict__ out) {
    __shared__ float sv[8];
    __shared__ int   si[8];
    __shared__ int   swin;

    const int row  = blockIdx.x;
    const int tid  = threadIdx.x;
    const int wid  = tid >> 5;
    const int lane = tid & 31;

    int cand = g_cand[row * 8 + wid];
    const float4* x4 = (const float4*)(x  + (size_t)row  * DIM);
    const float4* e4 = (const float4*)(cb + (size_t)cand * DIM);
    float s = 0.f;
#pragma unroll
    for (int i = 0; i < 4; i++) {
        float4 xv = x4[lane + i * 32];
        float4 ev = e4[lane + i * 32];
        float dx = xv.x - ev.x, dy = xv.y - ev.y;
        float dz = xv.z - ev.z, dw = xv.w - ev.w;
        s += dx * dx + dy * dy + dz * dz + dw * dw;
    }
#pragma unroll
    for (int o = 16; o > 0; o >>= 1) s += __shfl_down_sync(0xffffffffu, s, o);
    if (lane == 0) { sv[wid] = s; si[wid] = cand; }
    __syncthreads();

    if (tid == 0) {
        float bv = sv[0]; int bi = si[0];
#pragma unroll
        for (int k = 1; k < 8; k++) {
            float v = sv[k]; int ix = si[k];
            if (v < bv || (v == bv && ix < bi)) { bv = v; bi = ix; }
        }
        out[IDX_OFF + row] = (float)bi;
        out[MD_OFF + row]  = bv;
        swin = bi;
    }
    __syncthreads();

    if (tid < 128) {
        int win = swin;
        const float4* src = (const float4*)(cb + (size_t)win * DIM);
        float4*       dst = (float4*)(out + (size_t)row * DIM);
        dst[tid] = src[tid];
    }
}

// ---------------------------------------------------------------------------
// Kernel 4a/4b: deterministic two-stage loss reduction
// ---------------------------------------------------------------------------
__global__ void vq_loss1_kernel(const float* __restrict__ out) {
    __shared__ float s[256];
    int t = threadIdx.x;
    int base = blockIdx.x * 256;
    s[t] = out[MD_OFF + base + t];
    __syncthreads();
#pragma unroll
    for (int o = 128; o > 0; o >>= 1) {
        if (t < o) s[t] += s[t + o];
        __syncthreads();
    }
    if (t == 0) g_partial[blockIdx.x] = s[0];
}
__global__ void vq_loss2_kernel(float* __restrict__ out) {
    __shared__ float s[64];
    int t = threadIdx.x;
    s[t] = g_partial[t];
    __syncthreads();
#pragma unroll
    for (int o = 32; o > 0; o >>= 1) {
        if (t < o) s[t] += s[t + o];
        __syncthreads();
    }
    if (t == 0) {
        out[COMMIT_OFF] = s[0];
        out[LOSS_OFF]   = 1.25f * s[0];
    }
}

// ---------------------------------------------------------------------------
extern "C" void kernel_launch(void* const* d_in, const int* in_sizes, int n_in,
                              void* d_out, int out_size) {
    const float* x  = (const float*)d_in[0];   // [16384, 512]
    const float* cb = (const float*)d_in[1];   // [8192, 512]
    float* out = (float*)d_out;

    cudaFuncSetAttribute(vq_mma_kernel,
                         cudaFuncAttributeMaxDynamicSharedMemorySize, SMEM_DYN);

    split_x_kernel<<<NROWS * (DIM / 8) / 256, 256>>>(x);
    split_cb_kernel<<<NCODE / 8, 256>>>(cb);
    vq_mma_kernel<<<NCTA, 256, SMEM_DYN>>>();
    vq_refine_kernel<<<NROWS, 256>>>(x, cb, out);
    vq_loss1_kernel<<<64, 256>>>(out);
    vq_loss2_kernel<<<1, 64>>>(out);
}

// round 11
// speedup vs baseline: 2.7550x; 1.0285x over previous
#include <cuda_runtime.h>
#include <cuda_fp16.h>
#include <cstdint>

#define NROWS 16384
#define DIM   512
#define NCODE 8192

#define LOSS_OFF   8388608
#define IDX_OFF    8388609
#define MD_OFF     8404993
#define COMMIT_OFF 8421377

// 148 CTAs: 136 x 112 rows + 12 x 96 rows = 16384. One CTA per SM (one wave).
#define NCTA  148
#define NBIG  136
#define TMBIG 112
#define TMSML 96
#define BIGROWS_END 15232            // 136*112

#define TN   256
#define NKC  8                      // k-chunks of 64 per n-tile
#define NNT  (NCODE / TN)           // 32
#define TOTAL_CHUNKS (NNT * NKC)    // 256

// dynamic smem: A (max 112K) | B 2 x 32K | e2 1K | cand 14K | scand 3.5K | mbar
#define OFF_A    0
#define OFF_B    114688
#define BSTAGE   32768
#define OFF_E2   180224
#define OFF_CAND 181248             // 8 warps * 112 rows * 16B = 14336
#define OFF_SC   195584             // 112 rows * 8 cands * 4B = 3584
#define OFF_MB   199168
#define SMEM_DYN 199232

#define B_CHUNK  32768

__device__ float  g_e2[NCODE];
// chunk-major, pre-swizzled packed codebook: [nt*8+kc][rr 0..255][128B]
__device__ __half g_ch[NCODE * DIM];
__device__ float  g_partial[64];

// ---------------------------------------------------------------------------
__device__ __forceinline__ uint32_t smem_u32(const void* p) {
    uint32_t a;
    asm("{ .reg .u64 t; cvta.to.shared.u64 t, %1; cvt.u32.u64 %0, t; }"
        : "=r"(a) : "l"(p));
    return a;
}
__device__ __forceinline__ void ldsm4(uint32_t* r, uint32_t addr) {
    asm volatile("ldmatrix.sync.aligned.m8n8.x4.shared.b16 {%0,%1,%2,%3}, [%4];"
                 : "=r"(r[0]), "=r"(r[1]), "=r"(r[2]), "=r"(r[3]) : "r"(addr));
}
__device__ __forceinline__ void hmma16(uint32_t* c, const uint32_t* a,
                                       uint32_t b0, uint32_t b1) {
    asm volatile(
        "mma.sync.aligned.m16n8k16.row.col.f16.f16.f16.f16 "
        "{%0,%1}, {%2,%3,%4,%5}, {%6,%7}, {%0,%1};"
        : "+r"(c[0]), "+r"(c[1])
        : "r"(a[0]), "r"(a[1]), "r"(a[2]), "r"(a[3]), "r"(b0), "r"(b1));
}
__device__ __forceinline__ void bulk_g2s(uint32_t dst, const void* src,
                                         uint32_t bytes, uint32_t mbar) {
    asm volatile(
        "cp.async.bulk.shared::cluster.global.mbarrier::complete_tx::bytes "
        "[%0], [%1], %2, [%3];"
        :: "r"(dst), "l"(src), "r"(bytes), "r"(mbar) : "memory");
}
#define MBAR_INIT(mb, c) asm volatile("mbarrier.init.shared.b64 [%0], %1;" :: "r"(mb), "r"(c) : "memory")
#define MBAR_EXPECT(mb, tx) asm volatile("mbarrier.arrive.expect_tx.shared.b64 _, [%0], %1;" :: "r"(mb), "r"(tx) : "memory")
#define MBAR_WAIT(mb, ph) do {                                              \
    uint32_t _m = (mb), _p = (ph), _d;                                      \
    asm volatile("{ .reg .pred p; mbarrier.try_wait.parity.acquire.cta.shared::cta.b64 p, [%1], %2; selp.b32 %0,1,0,p; }" \
                 : "=r"(_d) : "r"(_m), "r"(_p) : "memory");                 \
    if (!_d) {                                                              \
        asm volatile("{ .reg .pred P1;\nW%=:\n"                             \
            "mbarrier.try_wait.parity.acquire.cta.shared::cta.b64 P1, [%0], %1, 0x989680;\n" \
            "@P1 bra.uni D%=;\nbra.uni W%=;\nD%=:\n}"                       \
            :: "r"(_m), "r"(_p) : "memory");                                \
    }                                                                       \
} while (0)

// ---------------------------------------------------------------------------
// Kernel 0: codebook fp16 pack (chunk-major swizzled) + fused exact norms
// ---------------------------------------------------------------------------
__global__ void split_cb_kernel(const float* __restrict__ cb) {
    int row  = (blockIdx.x * blockDim.x + threadIdx.x) >> 5;
    int lane = threadIdx.x & 31;
    if (row >= NCODE) return;
    const float4* r4 = (const float4*)(cb + (size_t)row * DIM);
    int nt = row >> 8, rr = row & 255;

    float s = 0.f;
#pragma unroll
    for (int q = 0; q < 2; q++) {
        int gg = lane + q * 32;
        float4 v0 = r4[gg * 2];
        float4 v1 = r4[gg * 2 + 1];
        s += v0.x * v0.x + v0.y * v0.y + v0.z * v0.z + v0.w * v0.w;
        s += v1.x * v1.x + v1.y * v1.y + v1.z * v1.z + v1.w * v1.w;
        __half2 h[4];
        h[0] = __halves2half2(__float2half_rn(v0.x), __float2half_rn(v0.y));
        h[1] = __halves2half2(__float2half_rn(v0.z), __float2half_rn(v0.w));
        h[2] = __halves2half2(__float2half_rn(v1.x), __float2half_rn(v1.y));
        h[3] = __halves2half2(__float2half_rn(v1.z), __float2half_rn(v1.w));
        int kc = gg >> 3, gi = gg & 7;
        size_t off = ((size_t)(nt * 8 + kc) * 256 + rr) * 128
                   + (size_t)((gi ^ (rr & 7)) << 4);
        *(uint4*)((char*)g_ch + off) = *(uint4*)h;
    }
#pragma unroll
    for (int o = 16; o > 0; o >>= 1) s += __shfl_down_sync(0xffffffffu, s, o);
    if (lane == 0) g_e2[row] = s;
}

// ---------------------------------------------------------------------------
// Kernel 1: fused GEMM (A converted in-prologue) + candidates + exact refine
//           + gather + outputs. 148 CTAs, 256 threads.
// ---------------------------------------------------------------------------
__global__ __launch_bounds__(256, 1)
void vq_mma_kernel(const float* __restrict__ x,
                   const float* __restrict__ cb,
                   float* __restrict__ out) {
    extern __shared__ __align__(1024) char smem[];
    const uint32_t sb = smem_u32(smem);
    float*  e2s   = (float*)(smem + OFF_E2);
    float4* cxf   = (float4*)(smem + OFF_CAND);
    int*    scand = (int*)(smem + OFF_SC);
    const uint32_t mbB0 = sb + OFF_MB;

    const int tid  = threadIdx.x;
    const int lane = tid & 31;
    const int wid  = tid >> 5;          // warp = 32-col slice
    const int blk  = blockIdx.x;

    const int ROWS    = (blk < NBIG) ? TMBIG : TMSML;
    const int MI      = (blk < NBIG) ? 7 : 6;
    const int rowbase = (blk < NBIG) ? blk * 112
                                     : BIGROWS_END + (blk - NBIG) * 96;
    const uint32_t ACH = (uint32_t)ROWS * 128;   // A chunk bytes per kc

    const int rA  = (lane & 7) + ((lane >> 3) & 1) * 8;
    const int cA  = lane >> 4;
    const int rB  = (lane & 7) + (lane >> 4) * 8;
    const int cB  = (lane >> 3) & 1;
    const int swl = lane & 7;
    const uint32_t bRow = (uint32_t)(wid * 32 + rB) * 128;
    const int g  = lane >> 2;
    const int t4 = lane & 3;

    // init running-candidate smem (top-2 per warp-slice per row)
    for (int idx = tid; idx < 8 * 112; idx += 256)
        cxf[idx] = make_float4(3.4e38f, 3.4e38f, 0.f, 0.f);

    if (tid == 0) {
        MBAR_INIT(mbB0, 1);
        MBAR_INIT(mbB0 + 8, 1);
    }
    __syncthreads();

    // B chunks 0,1 in flight first
    if (tid == 0) {
        MBAR_EXPECT(mbB0, B_CHUNK);
        bulk_g2s(sb + OFF_B, (const char*)g_ch, B_CHUNK, mbB0);
        MBAR_EXPECT(mbB0 + 8, B_CHUNK);
        bulk_g2s(sb + OFF_B + BSTAGE, (const char*)g_ch + B_CHUNK, B_CHUNK, mbB0 + 8);
    }

    // ---- prologue: convert this CTA's fp32 rows -> swizzled fp16 A in smem ----
    {
        const float4* x4 = (const float4*)x;
        const int ngroups = ROWS * 64;
        for (int idx = tid; idx < ngroups; idx += 256) {
            int rr = idx >> 6, gg = idx & 63;
            int kc = gg >> 3, gi = gg & 7;
            float4 v0 = x4[(size_t)(rowbase + rr) * 128 + gg * 2];
            float4 v1 = x4[(size_t)(rowbase + rr) * 128 + gg * 2 + 1];
            __half2 h[4];
            h[0] = __halves2half2(__float2half_rn(v0.x), __float2half_rn(v0.y));
            h[1] = __halves2half2(__float2half_rn(v0.z), __float2half_rn(v0.w));
            h[2] = __halves2half2(__float2half_rn(v1.x), __float2half_rn(v1.y));
            h[3] = __halves2half2(__float2half_rn(v1.z), __float2half_rn(v1.w));
            uint32_t off = (uint32_t)kc * ACH + (uint32_t)rr * 128
                         + (uint32_t)((gi ^ (rr & 7)) << 4);
            *(uint4*)(smem + OFF_A + off) = *(uint4*)h;
        }
    }
    __syncthreads();   // A ready for ldsm

    // fp16x2 accumulators: [mi][nj][pair]
    uint32_t acc[7][4][2];
#pragma unroll
    for (int a = 0; a < 7; a++)
#pragma unroll
        for (int b = 0; b < 4; b++) { acc[a][b][0] = 0u; acc[a][b][1] = 0u; }

#pragma unroll 1
    for (int cc = 0; cc < TOTAL_CHUNKS; cc++) {
        const int kc = cc & 7;
        const int stg = cc & 1;
        if (kc == 0) e2s[tid] = g_e2[(cc >> 3) * TN + tid];

        MBAR_WAIT(mbB0 + stg * 8, (cc >> 1) & 1);

        const uint32_t stB = sb + OFF_B + (uint32_t)stg * BSTAGE;
        const uint32_t stA = sb + OFF_A + (uint32_t)kc * ACH;
#pragma unroll
        for (int ks = 0; ks < 4; ks++) {
            uint32_t ah[7][4], bh[2][4];
            const uint32_t swA = (uint32_t)(((ks * 2 + cA) ^ swl) << 4);
            const uint32_t swB = (uint32_t)(((ks * 2 + cB) ^ swl) << 4);
#pragma unroll
            for (int np = 0; np < 2; np++)
                ldsm4(bh[np], stB + bRow + np * 2048 + swB);
#pragma unroll
            for (int mi = 0; mi < 7; mi++)
                if (mi < MI)
                    ldsm4(ah[mi], stA + (uint32_t)(mi * 16 + rA) * 128 + swA);
#pragma unroll
            for (int mi = 0; mi < 7; mi++)
                if (mi < MI)
#pragma unroll
                    for (int nj = 0; nj < 4; nj++)
                        hmma16(acc[mi][nj], ah[mi],
                               bh[nj >> 1][(nj & 1) * 2],
                               bh[nj >> 1][(nj & 1) * 2 + 1]);
        }

        if (kc == 7) {
            const int nt = cc >> 3;
#pragma unroll
            for (int mi = 0; mi < 7; mi++) {
                if (mi >= MI) continue;
#pragma unroll
                for (int p = 0; p < 2; p++) {
                    float v0 = 3.4e38f, v1 = 3.4e38f;
                    int   i0 = 0, i1 = 0;
#pragma unroll
                    for (int nj = 0; nj < 4; nj++) {
                        float2 f = __half22float2(*(__half2*)&acc[mi][nj][p]);
                        acc[mi][nj][p] = 0u;
#pragma unroll
                        for (int c = 0; c < 2; c++) {
                            int col = wid * 32 + nj * 8 + 2 * t4 + c;
                            float d = fmaf(-2.f, (c == 0) ? f.x : f.y, e2s[col]);
                            int gi = nt * TN + col;
                            bool lt1 = d < v1;
                            bool lt0 = d < v0;
                            v1 = lt0 ? v0 : (lt1 ? d : v1);
                            i1 = lt0 ? i0 : (lt1 ? gi : i1);
                            v0 = lt0 ? d : v0;
                            i0 = lt0 ? gi : i0;
                        }
                    }
#pragma unroll
                    for (int off = 1; off <= 2; off <<= 1) {
                        float w0 = __shfl_xor_sync(0xffffffffu, v0, off);
                        int   j0 = __shfl_xor_sync(0xffffffffu, i0, off);
                        float w1 = __shfl_xor_sync(0xffffffffu, v1, off);
                        int   j1 = __shfl_xor_sync(0xffffffffu, i1, off);
                        bool a = w0 < v0;
                        float h0 = a ? w0 : v0;  int hi0 = a ? j0 : i0;
                        float l0 = a ? v0 : w0;  int li0 = a ? i0 : j0;
                        float s  = a ? w1 : v1;  int si  = a ? j1 : i1;
                        bool b = l0 < s;
                        v0 = h0; i0 = hi0;
                        v1 = b ? l0 : s; i1 = b ? li0 : si;
                    }
                    if (t4 == 0) {
                        int rowin = mi * 16 + p * 8 + g;
                        float4 cur = cxf[wid * 112 + rowin];
                        float cv0 = cur.x, cv1 = cur.y;
                        int ci0 = __float_as_int(cur.z), ci1 = __float_as_int(cur.w);
                        bool a = v0 < cv0;
                        float h0 = a ? v0 : cv0; int hi0 = a ? i0 : ci0;
                        float l0 = a ? cv0 : v0; int li0 = a ? ci0 : i0;
                        float s  = a ? v1 : cv1; int si  = a ? i1 : ci1;
                        bool b = l0 < s;
                        cxf[wid * 112 + rowin] = make_float4(
                            h0, b ? l0 : s,
                            __int_as_float(hi0), __int_as_float(b ? li0 : si));
                    }
                }
            }
        }

        __syncthreads();
        if (tid == 0 && cc + 2 < TOTAL_CHUNKS) {
            MBAR_EXPECT(mbB0 + stg * 8, B_CHUNK);
            bulk_g2s(sb + OFF_B + (uint32_t)stg * BSTAGE,
                     (const char*)g_ch + (size_t)(cc + 2) * B_CHUNK,
                     B_CHUNK, mbB0 + stg * 8);
        }
    }

    // ---- merge warp pairs (2q, 2q+1) -> top-2 per 64-col quarter -> scand ----
    if (wid < 4) {
        const int q = wid;
#pragma unroll
        for (int j = 0; j < 4; j++) {
            int row = lane + j * 32;
            if (row < ROWS) {
                float4 A = cxf[(2 * q) * 112 + row];
                float4 B = cxf[(2 * q + 1) * 112 + row];
                float av0 = A.x, av1 = A.y, bv0 = B.x, bv1 = B.y;
                int ai0 = __float_as_int(A.z), ai1 = __float_as_int(A.w);
                int bi0 = __float_as_int(B.z), bi1 = __float_as_int(B.w);
                bool a = av0 < bv0;
                float h0 = a ? av0 : bv0; int hi0 = a ? ai0 : bi0;
                float l0 = a ? bv0 : av0; int li0 = a ? bi0 : ai0;
                float s  = a ? av1 : bv1; int si  = a ? ai1 : bi1;
                bool b = l0 < s;
                scand[row * 8 + q * 2 + 0] = hi0;
                scand[row * 8 + q * 2 + 1] = b ? li0 : si;
            }
        }
    }
    __syncthreads();

    // ---- fused exact fp32 refine + gather: warp per row, strided ----
    for (int r = wid; r < ROWS; r += 8) {
        const int grow = rowbase + r;
        const float4* x4 = (const float4*)(x + (size_t)grow * DIM);
        float4 xv[4];
#pragma unroll
        for (int i = 0; i < 4; i++) xv[i] = x4[lane + i * 32];

        float bv = 3.4e38f;
        int   bi = 0;
#pragma unroll
        for (int c = 0; c < 8; c++) {
            int cand = scand[r * 8 + c];
            const float4* e4 = (const float4*)(cb + (size_t)cand * DIM);
            float s = 0.f;
#pragma unroll
            for (int i = 0; i < 4; i++) {
                float4 ev = e4[lane + i * 32];
                float dx = xv[i].x - ev.x, dy = xv[i].y - ev.y;
                float dz = xv[i].z - ev.z, dw = xv[i].w - ev.w;
                s += dx * dx + dy * dy + dz * dz + dw * dw;
            }
#pragma unroll
            for (int o = 16; o > 0; o >>= 1)
                s += __shfl_xor_sync(0xffffffffu, s, o);
            if (s < bv || (s == bv && cand < bi)) { bv = s; bi = cand; }
        }
        if (lane == 0) {
            out[IDX_OFF + grow] = (float)bi;
            out[MD_OFF + grow]  = bv;
        }
        // gather winning codebook row -> quantized output
        const float4* src = (const float4*)(cb + (size_t)bi * DIM);
        float4*       dst = (float4*)(out + (size_t)grow * DIM);
#pragma unroll
        for (int i = 0; i < 4; i++) dst[lane + i * 32] = src[lane + i * 32];
    }
}

// ---------------------------------------------------------------------------
// Kernel 2a/2b: deterministic two-stage loss reduction
// ---------------------------------------------------------------------------
__global__ void vq_loss1_kernel(const float* __restrict__ out) {
    __shared__ float s[256];
    int t = threadIdx.x;
    int base = blockIdx.x * 256;
    s[t] = out[MD_OFF + base + t];
    __syncthreads();
#pragma unroll
    for (int o = 128; o > 0; o >>= 1) {
        if (t < o) s[t] += s[t + o];
        __syncthreads();
    }
    if (t == 0) g_partial[blockIdx.x] = s[0];
}
__global__ void vq_loss2_kernel(float* __restrict__ out) {
    __shared__ float s[64];
    int t = threadIdx.x;
    s[t] = g_partial[t];
    __syncthreads();
#pragma unroll
    for (int o = 32; o > 0; o >>= 1) {
        if (t < o) s[t] += s[t + o];
        __syncthreads();
    }
    if (t == 0) {
        out[COMMIT_OFF] = s[0];
        out[LOSS_OFF]   = 1.25f * s[0];
    }
}

// ---------------------------------------------------------------------------
extern "C" void kernel_launch(void* const* d_in, const int* in_sizes, int n_in,
                              void* d_out, int out_size) {
    const float* x  = (const float*)d_in[0];   // [16384, 512]
    const float* cb = (const float*)d_in[1];   // [8192, 512]
    float* out = (float*)d_out;

    cudaFuncSetAttribute(vq_mma_kernel,
                         cudaFuncAttributeMaxDynamicSharedMemorySize, SMEM_DYN);

    split_cb_kernel<<<NCODE / 8, 256>>>(cb);
    vq_mma_kernel<<<NCTA, 256, SMEM_DYN>>>(x, cb, out);
    vq_loss1_kernel<<<64, 256>>>(out);
    vq_loss2_kernel<<<1, 64>>>(out);
}

// round 12
// speedup vs baseline: 2.7703x; 1.0056x over previous
#include <cuda_runtime.h>
#include <cuda_fp16.h>
#include <cstdint>

#define NROWS 16384
#define DIM   512
#define NCODE 8192

#define LOSS_OFF   8388608
#define IDX_OFF    8388609
#define MD_OFF     8404993
#define COMMIT_OFF 8421377

// 148 CTAs: 136 x 112 rows + 12 x 96 rows = 16384. One CTA per SM (one wave).
#define NCTA  148
#define NBIG  136
#define TMBIG 112
#define TMSML 96
#define BIGROWS_END 15232            // 136*112

#define TN   256
#define NKC  8                      // k-chunks of 64 per n-tile
#define NNT  (NCODE / TN)           // 32
#define TOTAL_CHUNKS (NNT * NKC)    // 256

// dynamic smem: A (max 112K) | B 2 x 32K | e2 1K | cand 14K | scand 3.5K | mbar
#define OFF_A    0
#define OFF_B    114688
#define BSTAGE   32768
#define OFF_E2   180224
#define OFF_CAND 181248             // 8 warps * 112 rows * 16B = 14336
#define OFF_SC   195584             // 112 rows * 8 cands * 4B = 3584
#define OFF_MB   199168
#define SMEM_DYN 199232

#define B_CHUNK  32768

__device__ float  g_e2[NCODE];
// chunk-major, pre-swizzled packed codebook: [nt*8+kc][rr 0..255][128B]
__device__ __half g_ch[NCODE * DIM];
__device__ float  g_partial[NCTA];

// ---------------------------------------------------------------------------
__device__ __forceinline__ uint32_t smem_u32(const void* p) {
    uint32_t a;
    asm("{ .reg .u64 t; cvta.to.shared.u64 t, %1; cvt.u32.u64 %0, t; }"
        : "=r"(a) : "l"(p));
    return a;
}
__device__ __forceinline__ void ldsm4(uint32_t* r, uint32_t addr) {
    asm volatile("ldmatrix.sync.aligned.m8n8.x4.shared.b16 {%0,%1,%2,%3}, [%4];"
                 : "=r"(r[0]), "=r"(r[1]), "=r"(r[2]), "=r"(r[3]) : "r"(addr));
}
__device__ __forceinline__ void hmma16(uint32_t* c, const uint32_t* a,
                                       uint32_t b0, uint32_t b1) {
    asm volatile(
        "mma.sync.aligned.m16n8k16.row.col.f16.f16.f16.f16 "
        "{%0,%1}, {%2,%3,%4,%5}, {%6,%7}, {%0,%1};"
        : "+r"(c[0]), "+r"(c[1])
        : "r"(a[0]), "r"(a[1]), "r"(a[2]), "r"(a[3]), "r"(b0), "r"(b1));
}
__device__ __forceinline__ void bulk_g2s(uint32_t dst, const void* src,
                                         uint32_t bytes, uint32_t mbar) {
    asm volatile(
        "cp.async.bulk.shared::cluster.global.mbarrier::complete_tx::bytes "
        "[%0], [%1], %2, [%3];"
        :: "r"(dst), "l"(src), "r"(bytes), "r"(mbar) : "memory");
}
#define MBAR_INIT(mb, c) asm volatile("mbarrier.init.shared.b64 [%0], %1;" :: "r"(mb), "r"(c) : "memory")
#define MBAR_EXPECT(mb, tx) asm volatile("mbarrier.arrive.expect_tx.shared.b64 _, [%0], %1;" :: "r"(mb), "r"(tx) : "memory")
#define MBAR_WAIT(mb, ph) do {                                              \
    uint32_t _m = (mb), _p = (ph), _d;                                      \
    asm volatile("{ .reg .pred p; mbarrier.try_wait.parity.acquire.cta.shared::cta.b64 p, [%1], %2; selp.b32 %0,1,0,p; }" \
                 : "=r"(_d) : "r"(_m), "r"(_p) : "memory");                 \
    if (!_d) {                                                              \
        asm volatile("{ .reg .pred P1;\nW%=:\n"                             \
            "mbarrier.try_wait.parity.acquire.cta.shared::cta.b64 P1, [%0], %1, 0x989680;\n" \
            "@P1 bra.uni D%=;\nbra.uni W%=;\nD%=:\n}"                       \
            :: "r"(_m), "r"(_p) : "memory");                                \
    }                                                                       \
} while (0)

// ---------------------------------------------------------------------------
// Kernel 0: codebook fp16 pack (chunk-major swizzled) + fused exact norms
// ---------------------------------------------------------------------------
__global__ void split_cb_kernel(const float* __restrict__ cb) {
    int row  = (blockIdx.x * blockDim.x + threadIdx.x) >> 5;
    int lane = threadIdx.x & 31;
    if (row >= NCODE) return;
    const float4* r4 = (const float4*)(cb + (size_t)row * DIM);
    int nt = row >> 8, rr = row & 255;

    float s = 0.f;
#pragma unroll
    for (int q = 0; q < 2; q++) {
        int gg = lane + q * 32;
        float4 v0 = r4[gg * 2];
        float4 v1 = r4[gg * 2 + 1];
        s += v0.x * v0.x + v0.y * v0.y + v0.z * v0.z + v0.w * v0.w;
        s += v1.x * v1.x + v1.y * v1.y + v1.z * v1.z + v1.w * v1.w;
        __half2 h[4];
        h[0] = __halves2half2(__float2half_rn(v0.x), __float2half_rn(v0.y));
        h[1] = __halves2half2(__float2half_rn(v0.z), __float2half_rn(v0.w));
        h[2] = __halves2half2(__float2half_rn(v1.x), __float2half_rn(v1.y));
        h[3] = __halves2half2(__float2half_rn(v1.z), __float2half_rn(v1.w));
        int kc = gg >> 3, gi = gg & 7;
        size_t off = ((size_t)(nt * 8 + kc) * 256 + rr) * 128
                   + (size_t)((gi ^ (rr & 7)) << 4);
        *(uint4*)((char*)g_ch + off) = *(uint4*)h;
    }
#pragma unroll
    for (int o = 16; o > 0; o >>= 1) s += __shfl_down_sync(0xffffffffu, s, o);
    if (lane == 0) g_e2[row] = s;
}

// ---------------------------------------------------------------------------
// Kernel 1: fused GEMM + candidates + exact refine + gather + loss partials
// ---------------------------------------------------------------------------
__global__ __launch_bounds__(256, 1)
void vq_mma_kernel(const float* __restrict__ x,
                   const float* __restrict__ cb,
                   float* __restrict__ out) {
    extern __shared__ __align__(1024) char smem[];
    const uint32_t sb = smem_u32(smem);
    float*  e2s   = (float*)(smem + OFF_E2);
    float4* cxf   = (float4*)(smem + OFF_CAND);
    int*    scand = (int*)(smem + OFF_SC);
    const uint32_t mbB0 = sb + OFF_MB;

    const int tid  = threadIdx.x;
    const int lane = tid & 31;
    const int wid  = tid >> 5;          // warp = 32-col slice
    const int blk  = blockIdx.x;

    const int ROWS    = (blk < NBIG) ? TMBIG : TMSML;
    const int MI      = (blk < NBIG) ? 7 : 6;
    const int rowbase = (blk < NBIG) ? blk * 112
                                     : BIGROWS_END + (blk - NBIG) * 96;
    const uint32_t ACH = (uint32_t)ROWS * 128;   // A chunk bytes per kc

    const int rA  = (lane & 7) + ((lane >> 3) & 1) * 8;
    const int cA  = lane >> 4;
    const int rB  = (lane & 7) + (lane >> 4) * 8;
    const int cB  = (lane >> 3) & 1;
    const int swl = lane & 7;
    const uint32_t bRow = (uint32_t)(wid * 32 + rB) * 128;
    const int g  = lane >> 2;
    const int t4 = lane & 3;

    // init running-candidate smem (top-2 per warp-slice per row)
    for (int idx = tid; idx < 8 * 112; idx += 256)
        cxf[idx] = make_float4(3.4e38f, 3.4e38f, 0.f, 0.f);

    if (tid == 0) {
        MBAR_INIT(mbB0, 1);
        MBAR_INIT(mbB0 + 8, 1);
    }
    __syncthreads();

    // B chunks 0,1 in flight first
    if (tid == 0) {
        MBAR_EXPECT(mbB0, B_CHUNK);
        bulk_g2s(sb + OFF_B, (const char*)g_ch, B_CHUNK, mbB0);
        MBAR_EXPECT(mbB0 + 8, B_CHUNK);
        bulk_g2s(sb + OFF_B + BSTAGE, (const char*)g_ch + B_CHUNK, B_CHUNK, mbB0 + 8);
    }

    // ---- prologue: convert this CTA's fp32 rows -> swizzled fp16 A in smem ----
    {
        const float4* x4 = (const float4*)x;
        const int ngroups = ROWS * 64;
        for (int idx = tid; idx < ngroups; idx += 256) {
            int rr = idx >> 6, gg = idx & 63;
            int kc = gg >> 3, gi = gg & 7;
            float4 v0 = x4[(size_t)(rowbase + rr) * 128 + gg * 2];
            float4 v1 = x4[(size_t)(rowbase + rr) * 128 + gg * 2 + 1];
            __half2 h[4];
            h[0] = __halves2half2(__float2half_rn(v0.x), __float2half_rn(v0.y));
            h[1] = __halves2half2(__float2half_rn(v0.z), __float2half_rn(v0.w));
            h[2] = __halves2half2(__float2half_rn(v1.x), __float2half_rn(v1.y));
            h[3] = __halves2half2(__float2half_rn(v1.z), __float2half_rn(v1.w));
            uint32_t off = (uint32_t)kc * ACH + (uint32_t)rr * 128
                         + (uint32_t)((gi ^ (rr & 7)) << 4);
            *(uint4*)(smem + OFF_A + off) = *(uint4*)h;
        }
    }
    __syncthreads();   // A ready for ldsm

    // fp16x2 accumulators: [mi][nj][pair]
    uint32_t acc[7][4][2];
#pragma unroll
    for (int a = 0; a < 7; a++)
#pragma unroll
        for (int b = 0; b < 4; b++) { acc[a][b][0] = 0u; acc[a][b][1] = 0u; }

#pragma unroll 1
    for (int cc = 0; cc < TOTAL_CHUNKS; cc++) {
        const int kc = cc & 7;
        const int stg = cc & 1;
        if (kc == 0) e2s[tid] = g_e2[(cc >> 3) * TN + tid];

        MBAR_WAIT(mbB0 + stg * 8, (cc >> 1) & 1);

        const uint32_t stB = sb + OFF_B + (uint32_t)stg * BSTAGE;
        const uint32_t stA = sb + OFF_A + (uint32_t)kc * ACH;
#pragma unroll
        for (int ks = 0; ks < 4; ks++) {
            uint32_t ah[7][4], bh[2][4];
            const uint32_t swA = (uint32_t)(((ks * 2 + cA) ^ swl) << 4);
            const uint32_t swB = (uint32_t)(((ks * 2 + cB) ^ swl) << 4);
#pragma unroll
            for (int np = 0; np < 2; np++)
                ldsm4(bh[np], stB + bRow + np * 2048 + swB);
#pragma unroll
            for (int mi = 0; mi < 7; mi++)
                if (mi < MI)
                    ldsm4(ah[mi], stA + (uint32_t)(mi * 16 + rA) * 128 + swA);
#pragma unroll
            for (int mi = 0; mi < 7; mi++)
                if (mi < MI)
#pragma unroll
                    for (int nj = 0; nj < 4; nj++)
                        hmma16(acc[mi][nj], ah[mi],
                               bh[nj >> 1][(nj & 1) * 2],
                               bh[nj >> 1][(nj & 1) * 2 + 1]);
        }

        if (kc == 7) {
            const int nt = cc >> 3;
#pragma unroll
            for (int mi = 0; mi < 7; mi++) {
                if (mi >= MI) continue;
#pragma unroll
                for (int p = 0; p < 2; p++) {
                    float v0 = 3.4e38f, v1 = 3.4e38f;
                    int   i0 = 0, i1 = 0;
#pragma unroll
                    for (int nj = 0; nj < 4; nj++) {
                        float2 f = __half22float2(*(__half2*)&acc[mi][nj][p]);
                        acc[mi][nj][p] = 0u;
#pragma unroll
                        for (int c = 0; c < 2; c++) {
                            int col = wid * 32 + nj * 8 + 2 * t4 + c;
                            float d = fmaf(-2.f, (c == 0) ? f.x : f.y, e2s[col]);
                            int gi = nt * TN + col;
                            bool lt1 = d < v1;
                            bool lt0 = d < v0;
                            v1 = lt0 ? v0 : (lt1 ? d : v1);
                            i1 = lt0 ? i0 : (lt1 ? gi : i1);
                            v0 = lt0 ? d : v0;
                            i0 = lt0 ? gi : i0;
                        }
                    }
#pragma unroll
                    for (int off = 1; off <= 2; off <<= 1) {
                        float w0 = __shfl_xor_sync(0xffffffffu, v0, off);
                        int   j0 = __shfl_xor_sync(0xffffffffu, i0, off);
                        float w1 = __shfl_xor_sync(0xffffffffu, v1, off);
                        int   j1 = __shfl_xor_sync(0xffffffffu, i1, off);
                        bool a = w0 < v0;
                        float h0 = a ? w0 : v0;  int hi0 = a ? j0 : i0;
                        float l0 = a ? v0 : w0;  int li0 = a ? i0 : j0;
                        float s  = a ? w1 : v1;  int si  = a ? j1 : i1;
                        bool b = l0 < s;
                        v0 = h0; i0 = hi0;
                        v1 = b ? l0 : s; i1 = b ? li0 : si;
                    }
                    if (t4 == 0) {
                        int rowin = mi * 16 + p * 8 + g;
                        float4 cur = cxf[wid * 112 + rowin];
                        float cv0 = cur.x, cv1 = cur.y;
                        int ci0 = __float_as_int(cur.z), ci1 = __float_as_int(cur.w);
                        bool a = v0 < cv0;
                        float h0 = a ? v0 : cv0; int hi0 = a ? i0 : ci0;
                        float l0 = a ? cv0 : v0; int li0 = a ? ci0 : i0;
                        float s  = a ? v1 : cv1; int si  = a ? i1 : ci1;
                        bool b = l0 < s;
                        cxf[wid * 112 + rowin] = make_float4(
                            h0, b ? l0 : s,
                            __int_as_float(hi0), __int_as_float(b ? li0 : si));
                    }
                }
            }
        }

        __syncthreads();
        if (tid == 0 && cc + 2 < TOTAL_CHUNKS) {
            MBAR_EXPECT(mbB0 + stg * 8, B_CHUNK);
            bulk_g2s(sb + OFF_B + (uint32_t)stg * BSTAGE,
                     (const char*)g_ch + (size_t)(cc + 2) * B_CHUNK,
                     B_CHUNK, mbB0 + stg * 8);
        }
    }

    // ---- merge warp pairs (2q, 2q+1) -> top-2 per 64-col quarter -> scand ----
    if (wid < 4) {
        const int q = wid;
#pragma unroll
        for (int j = 0; j < 4; j++) {
            int row = lane + j * 32;
            if (row < ROWS) {
                float4 A = cxf[(2 * q) * 112 + row];
                float4 B = cxf[(2 * q + 1) * 112 + row];
                float av0 = A.x, av1 = A.y, bv0 = B.x, bv1 = B.y;
                int ai0 = __float_as_int(A.z), ai1 = __float_as_int(A.w);
                int bi0 = __float_as_int(B.z), bi1 = __float_as_int(B.w);
                bool a = av0 < bv0;
                float h0 = a ? av0 : bv0; int hi0 = a ? ai0 : bi0;
                float l0 = a ? bv0 : av0; int li0 = a ? bi0 : ai0;
                float s  = a ? av1 : bv1; int si  = a ? ai1 : bi1;
                bool b = l0 < s;
                scand[row * 8 + q * 2 + 0] = hi0;
                scand[row * 8 + q * 2 + 1] = b ? li0 : si;
            }
        }
    }
    __syncthreads();

    // ---- fused exact fp32 refine + gather + per-warp loss partial ----
    float wsum = 0.f;
    for (int r = wid; r < ROWS; r += 8) {
        const int grow = rowbase + r;
        const float4* x4 = (const float4*)(x + (size_t)grow * DIM);
        float4 xv[4];
#pragma unroll
        for (int i = 0; i < 4; i++) xv[i] = x4[lane + i * 32];

        float bv = 3.4e38f;
        int   bi = 0;
#pragma unroll
        for (int c = 0; c < 8; c++) {
            int cand = scand[r * 8 + c];
            const float4* e4 = (const float4*)(cb + (size_t)cand * DIM);
            float s = 0.f;
#pragma unroll
            for (int i = 0; i < 4; i++) {
                float4 ev = e4[lane + i * 32];
                float dx = xv[i].x - ev.x, dy = xv[i].y - ev.y;
                float dz = xv[i].z - ev.z, dw = xv[i].w - ev.w;
                s += dx * dx + dy * dy + dz * dz + dw * dw;
            }
#pragma unroll
            for (int o = 16; o > 0; o >>= 1)
                s += __shfl_xor_sync(0xffffffffu, s, o);
            if (s < bv || (s == bv && cand < bi)) { bv = s; bi = cand; }
        }
        wsum += bv;
        if (lane == 0) {
            out[IDX_OFF + grow] = (float)bi;
            out[MD_OFF + grow]  = bv;
        }
        // gather winning codebook row -> quantized output
        const float4* src = (const float4*)(cb + (size_t)bi * DIM);
        float4*       dst = (float4*)(out + (size_t)grow * DIM);
#pragma unroll
        for (int i = 0; i < 4; i++) dst[lane + i * 32] = src[lane + i * 32];
    }

    // per-CTA loss partial (e2s reused as scratch; safe after mainloop)
    if (lane == 0) e2s[wid] = wsum;
    __syncthreads();
    if (tid == 0) {
        float s = 0.f;
#pragma unroll
        for (int w = 0; w < 8; w++) s += e2s[w];
        g_partial[blk] = s;
    }
}

// ---------------------------------------------------------------------------
// Kernel 2: final deterministic loss reduction over 148 CTA partials
// ---------------------------------------------------------------------------
__global__ void vq_loss_kernel(float* __restrict__ out) {
    __shared__ float s[256];
    int t = threadIdx.x;
    s[t] = (t < NCTA) ? g_partial[t] : 0.f;
    __syncthreads();
#pragma unroll
    for (int o = 128; o > 0; o >>= 1) {
        if (t < o) s[t] += s[t + o];
        __syncthreads();
    }
    if (t == 0) {
        out[COMMIT_OFF] = s[0];
        out[LOSS_OFF]   = 1.25f * s[0];
    }
}

// ---------------------------------------------------------------------------
extern "C" void kernel_launch(void* const* d_in, const int* in_sizes, int n_in,
                              void* d_out, int out_size) {
    const float* x  = (const float*)d_in[0];   // [16384, 512]
    const float* cb = (const float*)d_in[1];   // [8192, 512]
    float* out = (float*)d_out;

    cudaFuncSetAttribute(vq_mma_kernel,
                         cudaFuncAttributeMaxDynamicSharedMemorySize, SMEM_DYN);

    split_cb_kernel<<<NCODE / 16, 512>>>(cb);
    vq_mma_kernel<<<NCTA, 256, SMEM_DYN>>>(x, cb, out);
    vq_loss_kernel<<<1, 256>>>(out);
}